// round 11
// baseline (speedup 1.0000x reference)
#include <cuda_runtime.h>
#include <cuda_bf16.h>
#include <math.h>
#include <stdint.h>

#define BB 32
#define SSQ 128
#define EE 256
#define UU 256
#define VV 32000
#define RR (BB*SSQ)   // 4096

// ---------------- device scratch ----------------
__device__ float g_gx_enc[RR * 768];
__device__ float g_gx_dec[RR * 768];
__device__ float g_enc_out[RR * UU];
__device__ float g_enc_proj[RR * UU];
__device__ float g_P[RR * 768];
__device__ float g_Hdec[RR * UU];
__device__ float g_zb[768];                  // zero bias
__device__ __nv_bfloat16 g_A2[(size_t)RR * 512];
__device__ __nv_bfloat16 g_B2[(size_t)VV * 512];

__device__ __forceinline__ float sigmoidf_(float x) { return 1.0f / (1.0f + __expf(-x)); }
__device__ __forceinline__ float tanhapx(float x) {
    float y; asm("tanh.approx.f32 %0, %1;" : "=f"(y) : "f"(x)); return y;
}
__device__ __forceinline__ unsigned smem_u32(const void* p) {
    return (unsigned)__cvta_generic_to_shared(p);
}
#define CP_ASYNC16(saddr, gptr) \
    asm volatile("cp.async.ca.shared.global [%0], [%1], 16;" :: "r"(saddr), "l"(gptr))
#define CP_COMMIT()  asm volatile("cp.async.commit_group;")
#define CP_WAIT0()   asm volatile("cp.async.wait_group 0;")

#define MMA_BF16(c0, c1, c2, c3, a0, a1, a2, a3, b0, b1) \
    asm volatile("mma.sync.aligned.m16n8k16.row.col.f32.bf16.bf16.f32 " \
                 "{%0,%1,%2,%3}, {%4,%5,%6,%7}, {%8,%9}, {%0,%1,%2,%3};" \
                 : "+f"(c0), "+f"(c1), "+f"(c2), "+f"(c3) \
                 : "r"(a0), "r"(a1), "r"(a2), "r"(a3), "r"(b0), "r"(b1))

// ---------------- Wfc transpose + bf16 hi/lo split ----------------
__global__ __launch_bounds__(256)
void k_wconv(const float* __restrict__ W, __nv_bfloat16* __restrict__ B2) {
    __shared__ float tile[64][65];
    const int n0 = blockIdx.x * 64, k0 = blockIdx.y * 64;
    for (int i = threadIdx.x; i < 4096; i += 256) {
        int r = i >> 6, c = i & 63;
        tile[r][c] = W[(size_t)(k0 + r) * VV + n0 + c];
    }
    __syncthreads();
    for (int i = threadIdx.x; i < 4096; i += 256) {
        int r = i >> 6, c = i & 63;
        float v = tile[c][r];
        __nv_bfloat16 h = __float2bfloat16(v);
        __nv_bfloat16 l = __float2bfloat16(v - __bfloat162float(h));
        size_t base = (size_t)(n0 + r) * 512 + k0 + c;
        B2[base] = h;
        B2[base + 256] = l;
    }
}

// ---------------- Hdec -> A2 hi|lo ----------------
__global__ __launch_bounds__(512)
void k_hconv(const float* __restrict__ H, __nv_bfloat16* __restrict__ A2) {
    int i = (blockIdx.x * 512 + threadIdx.x) * 4;
    int row = i >> 8, k = i & 255;
    float4 v = *(const float4*)(H + i);
    __nv_bfloat16 h0 = __float2bfloat16(v.x), h1 = __float2bfloat16(v.y);
    __nv_bfloat16 h2 = __float2bfloat16(v.z), h3 = __float2bfloat16(v.w);
    __nv_bfloat16 l0 = __float2bfloat16(v.x - __bfloat162float(h0));
    __nv_bfloat16 l1 = __float2bfloat16(v.y - __bfloat162float(h1));
    __nv_bfloat16 l2 = __float2bfloat16(v.z - __bfloat162float(h2));
    __nv_bfloat16 l3 = __float2bfloat16(v.w - __bfloat162float(h3));
    __nv_bfloat162 ph0 = __halves2bfloat162(h0, h1), ph1 = __halves2bfloat162(h2, h3);
    __nv_bfloat162 pl0 = __halves2bfloat162(l0, l1), pl1 = __halves2bfloat162(l2, l3);
    size_t base = (size_t)row * 512 + k;
    *(uint2*)(A2 + base)       = make_uint2(*(uint32_t*)&ph0, *(uint32_t*)&ph1);
    *(uint2*)(A2 + base + 256) = make_uint2(*(uint32_t*)&pl0, *(uint32_t*)&pl1);
}

// ---------------- FC via HMMA 3-term split ----------------
#define FCP 144
#define FC_A_BYTES (128 * FCP)
#define FC_STAGE   (2 * FC_A_BYTES)

__device__ __forceinline__ void fc_load(char* sbase, const char* Ag, const char* Bg,
                                        int ca, int cb, int t) {
    const int ar = t >> 1, ac0 = (t & 1) * 4;
#pragma unroll
    for (int i = 0; i < 4; i++) {
        const int col16 = ac0 + i;
        const uint32_t off = (uint32_t)(ar * FCP + col16 * 16);
        CP_ASYNC16(smem_u32(sbase + off),              Ag + (size_t)ar * 1024 + ca * 128 + col16 * 16);
        CP_ASYNC16(smem_u32(sbase + FC_A_BYTES + off), Bg + (size_t)ar * 1024 + cb * 128 + col16 * 16);
    }
}

__global__ __launch_bounds__(256, 2)
void k_fc_mma(const __nv_bfloat16* __restrict__ A2, const __nv_bfloat16* __restrict__ B2,
              const float* __restrict__ bias, float* __restrict__ out) {
    extern __shared__ char smem[];
    const int t = threadIdx.x, lane = t & 31, wid = t >> 5;
    const int bm = blockIdx.y * 128, bn = blockIdx.x * 128;
    const int wm = wid & 3, wn = wid >> 2;
    const int qr = lane >> 2;
    const int qc = (lane & 3) * 2;

    const char* Ag = (const char*)(A2 + (size_t)bm * 512);
    const char* Bg = (const char*)(B2 + (size_t)bn * 512);

    float acc[2][8][4];
#pragma unroll
    for (int mf = 0; mf < 2; mf++)
#pragma unroll
        for (int nf = 0; nf < 8; nf++)
#pragma unroll
            for (int j = 0; j < 4; j++) acc[mf][nf][j] = 0.f;

    fc_load(smem, Ag, Bg, 0, 0, t);
    CP_COMMIT(); CP_WAIT0();
    __syncthreads();

    for (int c = 0; c < 12; c++) {
        const int buf = c & 1;
        if (c < 11) {
            const int p = c + 1, g = p >> 2, j = p & 3;
            fc_load(smem + (buf ^ 1) * FC_STAGE, Ag, Bg,
                    j + ((g == 2) ? 4 : 0), j + ((g == 1) ? 4 : 0), t);
            CP_COMMIT();
        }
        const char* Ab = smem + buf * FC_STAGE;
        const char* Bb = Ab + FC_A_BYTES;

#pragma unroll
        for (int ks = 0; ks < 4; ks++) {
            const int kb = (ks * 16 + qc) * 2;
            uint32_t a[2][4];
#pragma unroll
            for (int mf = 0; mf < 2; mf++) {
                const char* ap = Ab + (wm * 32 + mf * 16 + qr) * FCP + kb;
                a[mf][0] = *(const uint32_t*)(ap);
                a[mf][1] = *(const uint32_t*)(ap + 8 * FCP);
                a[mf][2] = *(const uint32_t*)(ap + 16);
                a[mf][3] = *(const uint32_t*)(ap + 8 * FCP + 16);
            }
            uint32_t bfr[8][2];
#pragma unroll
            for (int nf = 0; nf < 8; nf++) {
                const char* bp = Bb + (wn * 64 + nf * 8 + qr) * FCP + kb;
                bfr[nf][0] = *(const uint32_t*)(bp);
                bfr[nf][1] = *(const uint32_t*)(bp + 16);
            }
#pragma unroll
            for (int mf = 0; mf < 2; mf++)
#pragma unroll
                for (int nf = 0; nf < 8; nf++)
                    MMA_BF16(acc[mf][nf][0], acc[mf][nf][1], acc[mf][nf][2], acc[mf][nf][3],
                             a[mf][0], a[mf][1], a[mf][2], a[mf][3],
                             bfr[nf][0], bfr[nf][1]);
        }
        if (c < 11) CP_WAIT0();
        __syncthreads();
    }

#pragma unroll
    for (int mf = 0; mf < 2; mf++) {
        const int m0 = bm + wm * 32 + mf * 16 + qr;
#pragma unroll
        for (int nf = 0; nf < 8; nf++) {
            const int n = bn + wn * 64 + nf * 8 + qc;
            const float2 bv = *(const float2*)(bias + n);
            float2 o0, o1;
            o0.x = acc[mf][nf][0] + bv.x; o0.y = acc[mf][nf][1] + bv.y;
            o1.x = acc[mf][nf][2] + bv.x; o1.y = acc[mf][nf][3] + bv.y;
            *(float2*)(out + (size_t)m0 * VV + n) = o0;
            *(float2*)(out + (size_t)(m0 + 8) * VV + n) = o1;
        }
    }
}

// ---------------- fp32 GEMM body (device) ----------------
struct SmemGemm { float As[2][16][128]; float Bs[2][16][128]; };

template<int GATHER>
__device__ __forceinline__
void gemm_body(SmemGemm& sm, const float* __restrict__ A, const float* __restrict__ B,
               const float* __restrict__ bias, float* __restrict__ C,
               int N, int K, const int* __restrict__ toks, int bm, int bn) {
    const int t = threadIdx.x;
    const int arow = t >> 1, ak = (t & 1) * 8;
    const int brow = t >> 5, bcol = (t & 31) * 4;
    const int tm0 = (t >> 4) * 8, tn0 = (t & 15) * 8;

    const float* Abase;
    if (GATHER == 0) {
        Abase = A + (size_t)(bm + arow) * K;
    } else {
        int r = bm + arow, s = r >> 5, b = r & 31;
        int tok;
        if (GATHER == 1) tok = toks[b * SSQ + s];
        else             tok = (s == 0) ? 0 : toks[b * SSQ + s - 1];
        Abase = A + (size_t)tok * K;
    }
    const float* Bbase = B + (size_t)brow * N + bn + bcol;

    float acc[8][8];
#pragma unroll
    for (int i = 0; i < 8; i++)
#pragma unroll
        for (int j = 0; j < 8; j++) acc[i][j] = 0.f;

    float4 av0 = *(const float4*)(Abase + ak);
    float4 av1 = *(const float4*)(Abase + ak + 4);
    CP_ASYNC16(smem_u32(&sm.Bs[0][brow][bcol]), Bbase);
    CP_ASYNC16(smem_u32(&sm.Bs[0][brow + 8][bcol]), Bbase + (size_t)8 * N);
    CP_COMMIT();
    sm.As[0][ak + 0][arow] = av0.x; sm.As[0][ak + 1][arow] = av0.y;
    sm.As[0][ak + 2][arow] = av0.z; sm.As[0][ak + 3][arow] = av0.w;
    sm.As[0][ak + 4][arow] = av1.x; sm.As[0][ak + 5][arow] = av1.y;
    sm.As[0][ak + 6][arow] = av1.z; sm.As[0][ak + 7][arow] = av1.w;
    CP_WAIT0();
    __syncthreads();

    const int NT = K >> 4;
    for (int kt = 0; kt < NT; kt++) {
        const int buf = kt & 1, nxt = buf ^ 1;
        const bool more = (kt + 1 < NT);
        if (more) {
            const float* Ap = Abase + (kt + 1) * 16;
            av0 = *(const float4*)(Ap + ak);
            av1 = *(const float4*)(Ap + ak + 4);
            const float* Bp = Bbase + (size_t)(kt + 1) * 16 * N;
            CP_ASYNC16(smem_u32(&sm.Bs[nxt][brow][bcol]), Bp);
            CP_ASYNC16(smem_u32(&sm.Bs[nxt][brow + 8][bcol]), Bp + (size_t)8 * N);
            CP_COMMIT();
        }
#pragma unroll
        for (int kk = 0; kk < 16; kk++) {
            float a[8], bf[8];
            *(float4*)&a[0]  = *(const float4*)&sm.As[buf][kk][tm0];
            *(float4*)&a[4]  = *(const float4*)&sm.As[buf][kk][tm0 + 4];
            *(float4*)&bf[0] = *(const float4*)&sm.Bs[buf][kk][tn0];
            *(float4*)&bf[4] = *(const float4*)&sm.Bs[buf][kk][tn0 + 4];
#pragma unroll
            for (int i = 0; i < 8; i++)
#pragma unroll
                for (int j = 0; j < 8; j++)
                    acc[i][j] = fmaf(a[i], bf[j], acc[i][j]);
        }
        if (more) {
            sm.As[nxt][ak + 0][arow] = av0.x; sm.As[nxt][ak + 1][arow] = av0.y;
            sm.As[nxt][ak + 2][arow] = av0.z; sm.As[nxt][ak + 3][arow] = av0.w;
            sm.As[nxt][ak + 4][arow] = av1.x; sm.As[nxt][ak + 5][arow] = av1.y;
            sm.As[nxt][ak + 6][arow] = av1.z; sm.As[nxt][ak + 7][arow] = av1.w;
            CP_WAIT0();
        }
        __syncthreads();
    }

#pragma unroll
    for (int i = 0; i < 8; i++) {
        float* Crow = C + (size_t)(bm + tm0 + i) * N + bn + tn0;
#pragma unroll
        for (int j = 0; j < 8; j += 4) {
            float4 o;
            o.x = acc[i][j + 0] + bias[bn + tn0 + j + 0];
            o.y = acc[i][j + 1] + bias[bn + tn0 + j + 1];
            o.z = acc[i][j + 2] + bias[bn + tn0 + j + 2];
            o.w = acc[i][j + 3] + bias[bn + tn0 + j + 3];
            *(float4*)(Crow + j) = o;
        }
    }
}

// dual-GEMM 1: gx_enc (blocks x<6, GATHER=1) + gx_dec (blocks x>=6, GATHER=2)
__global__ __launch_bounds__(256, 2)
void k_gx_dual(const float* __restrict__ enc_embed, const float* __restrict__ enc_Wx,
               const float* __restrict__ enc_b, float* __restrict__ gxe,
               const float* __restrict__ dec_embed, const float* __restrict__ dec_WxE,
               const float* __restrict__ dec_b, float* __restrict__ gxd,
               const int* __restrict__ x, const int* __restrict__ labels) {
    __shared__ SmemGemm sm;
    const int bm = blockIdx.y * 128;
    if (blockIdx.x < 6)
        gemm_body<1>(sm, enc_embed, enc_Wx, enc_b, gxe, 768, 256, x, bm, blockIdx.x * 128);
    else
        gemm_body<2>(sm, dec_embed, dec_WxE, dec_b, gxd, 768, 256, labels, bm, (blockIdx.x - 6) * 128);
}

// dual-GEMM 2: enc_proj (blocks x<2) + P (blocks x>=2)
__global__ __launch_bounds__(256, 2)
void k_proj_dual(const float* __restrict__ eo,
                 const float* __restrict__ W1, const float* __restrict__ b1, float* __restrict__ ep,
                 const float* __restrict__ dec_Wx, const float* __restrict__ zb, float* __restrict__ P) {
    __shared__ SmemGemm sm;
    const int bm = blockIdx.y * 128;
    if (blockIdx.x < 2)
        gemm_body<0>(sm, eo, W1, b1, ep, 256, 256, nullptr, bm, blockIdx.x * 128);
    else
        gemm_body<0>(sm, eo, dec_Wx, zb, P, 768, 256, nullptr, bm, (blockIdx.x - 2) * 128);
}

// ---------------- encoder GRU: 8-deep register staging (no spill) ----------------
__global__ __launch_bounds__(512)
void k_encoder(const float* __restrict__ gx, const float* __restrict__ Wh,
               float* __restrict__ enc_out) {
    __shared__ float sh_h[2][UU];
    __shared__ float sp[2][768];
    const int b = blockIdx.x, t = threadIdx.x;
    float h_old = 0.f;
    if (t < 256) sh_h[0][t] = 0.f;
    __syncthreads();
    for (int s = 0; s < SSQ; s++) {
        const int cur = s & 1;
        if (t < 384) {
            const int half = (t >= 192), c = t - half * 192;
            const float4* W4 = (const float4*)Wh + c;
            float4 acc = make_float4(0.f, 0.f, 0.f, 0.f);
            const int k0 = half * 128;
            for (int kb = 0; kb < 128; kb += 8) {
                float4 wv[8];
#pragma unroll
                for (int i = 0; i < 8; i++) wv[i] = W4[(size_t)(k0 + kb + i) * 192];
#pragma unroll
                for (int i = 0; i < 8; i++) {
                    float hk = sh_h[cur][k0 + kb + i];
                    acc.x = fmaf(hk, wv[i].x, acc.x); acc.y = fmaf(hk, wv[i].y, acc.y);
                    acc.z = fmaf(hk, wv[i].z, acc.z); acc.w = fmaf(hk, wv[i].w, acc.w);
                }
            }
            ((float4*)sp[half])[c] = acc;
        }
        __syncthreads();
        if (t < 256) {
            const float* gxr = gx + (size_t)(s * 32 + b) * 768;
            float z  = sigmoidf_(gxr[t]       + sp[0][t]       + sp[1][t]);
            float r  = sigmoidf_(gxr[256 + t] + sp[0][256 + t] + sp[1][256 + t]);
            float hh = tanhf(gxr[512 + t] + r * (sp[0][512 + t] + sp[1][512 + t]));
            float hn = z * h_old + (1.f - z) * hh;
            h_old = hn;
            enc_out[(size_t)(b * SSQ + s) * UU + t] = hn;
            sh_h[cur ^ 1][t] = hn;
        }
        __syncthreads();
    }
}

// ---------------- decoder: 8-deep staging everywhere ----------------
__global__ __launch_bounds__(512)
void k_decoder(const float* __restrict__ enc_proj, const float* __restrict__ P,
               const float* __restrict__ gx, const float* __restrict__ dec_Wh,
               const float* __restrict__ W2, const float* __restrict__ b2,
               const float* __restrict__ Va, const float* __restrict__ ba,
               const float* __restrict__ enc_out, float* __restrict__ Hdec) {
    __shared__ float sh_h[2][UU];
    __shared__ float sh_Va[UU];
    __shared__ float sh_sc[SSQ];
    __shared__ float sh_w[SSQ];
    __shared__ float sp_q[2][UU];
    __shared__ float sp_gh[2][768];
    __shared__ float sp_gx[2][768];
    __shared__ float sred[8];

    const int b = blockIdx.x, t = threadIdx.x;
    float h_old = 0.f;
    if (t < 256) {
        sh_Va[t] = Va[t];
        h_old = enc_out[(size_t)(b * SSQ + 127) * UU + t];
        sh_h[0][t] = h_old;
    }
    const float ba0 = ba[0];
    __syncthreads();

    for (int ts = 0; ts < SSQ; ts++) {
        const int cur = ts & 1;
        // ---- Phase A: q = h@W2 (t<128) || gh = h@Wh (t in [128,512)) ----
        if (t < 128) {
            const int c = t & 63, half = t >> 6;
            const float4* W4 = (const float4*)W2 + c;
            float4 acc = make_float4(0.f, 0.f, 0.f, 0.f);
            const int k0 = half * 128;
            for (int kb = 0; kb < 128; kb += 8) {
                float4 wv[8];
#pragma unroll
                for (int i = 0; i < 8; i++) wv[i] = W4[(size_t)(k0 + kb + i) * 64];
#pragma unroll
                for (int i = 0; i < 8; i++) {
                    float hk = sh_h[cur][k0 + kb + i];
                    acc.x = fmaf(hk, wv[i].x, acc.x); acc.y = fmaf(hk, wv[i].y, acc.y);
                    acc.z = fmaf(hk, wv[i].z, acc.z); acc.w = fmaf(hk, wv[i].w, acc.w);
                }
            }
            if (half == 0) {
                float4 bb = ((const float4*)b2)[c];
                acc.x += bb.x; acc.y += bb.y; acc.z += bb.z; acc.w += bb.w;
            }
            ((float4*)sp_q[half])[c] = acc;
        } else {
            const int u = t - 128;
            const int c = u % 192, half = u / 192;
            const float4* Wh4 = (const float4*)dec_Wh + c;
            float4 acc = make_float4(0.f, 0.f, 0.f, 0.f);
            const int k0 = half * 128;
            for (int kb = 0; kb < 128; kb += 8) {
                float4 wv[8];
#pragma unroll
                for (int i = 0; i < 8; i++) wv[i] = Wh4[(size_t)(k0 + kb + i) * 192];
#pragma unroll
                for (int i = 0; i < 8; i++) {
                    float hk = sh_h[cur][k0 + kb + i];
                    acc.x = fmaf(hk, wv[i].x, acc.x); acc.y = fmaf(hk, wv[i].y, acc.y);
                    acc.z = fmaf(hk, wv[i].z, acc.z); acc.w = fmaf(hk, wv[i].w, acc.w);
                }
            }
            ((float4*)sp_gh[half])[c] = acc;
        }
        __syncthreads();

        // ---- attention scores ----
        {
            const int s = t >> 2, qd = t & 3;
            const float4* ep = (const float4*)(enc_proj + (size_t)(b * SSQ + s) * UU) + qd * 16;
            const float4* q0 = (const float4*)sp_q[0] + qd * 16;
            const float4* q1 = (const float4*)sp_q[1] + qd * 16;
            const float4* v4 = (const float4*)sh_Va + qd * 16;
            float acc = 0.f;
#pragma unroll 8
            for (int i = 0; i < 16; i++) {
                float4 p = ep[i], qa = q0[i], qb = q1[i], vv = v4[i];
                acc += tanhapx(p.x + qa.x + qb.x) * vv.x;
                acc += tanhapx(p.y + qa.y + qb.y) * vv.y;
                acc += tanhapx(p.z + qa.z + qb.z) * vv.z;
                acc += tanhapx(p.w + qa.w + qb.w) * vv.w;
            }
            acc += __shfl_xor_sync(0xffffffffu, acc, 1);
            acc += __shfl_xor_sync(0xffffffffu, acc, 2);
            if (qd == 0) sh_sc[s] = acc + ba0;
        }
        __syncthreads();

        // ---- softmax ----
        {
            float v = (t < 128) ? sh_sc[t] : -1e30f;
            float m = v;
#pragma unroll
            for (int o = 16; o; o >>= 1) m = fmaxf(m, __shfl_xor_sync(0xffffffffu, m, o));
            if (t < 128 && (t & 31) == 0) sred[t >> 5] = m;
            __syncthreads();
            float gm = fmaxf(fmaxf(sred[0], sred[1]), fmaxf(sred[2], sred[3]));
            float e = (t < 128) ? __expf(v - gm) : 0.f;
            float ssum = e;
#pragma unroll
            for (int o = 16; o; o >>= 1) ssum += __shfl_xor_sync(0xffffffffu, ssum, o);
            __syncthreads();
            if (t < 128 && (t & 31) == 0) sred[t >> 5] = ssum;
            __syncthreads();
            float gs = sred[0] + sred[1] + sred[2] + sred[3];
            if (t < 128) sh_w[t] = e / gs;
        }
        __syncthreads();

        // ---- gxP = sum_s w[s] * P[b,s,:] ----
        if (t < 384) {
            const int half = (t >= 192), c = t - half * 192;
            const float4* P4 = (const float4*)(P + (size_t)(b * SSQ) * 768) + c;
            float4 acc = make_float4(0.f, 0.f, 0.f, 0.f);
            const int s0 = half * 64;
            for (int sb = 0; sb < 64; sb += 8) {
                float4 pv[8];
#pragma unroll
                for (int i = 0; i < 8; i++) pv[i] = P4[(size_t)(s0 + sb + i) * 192];
#pragma unroll
                for (int i = 0; i < 8; i++) {
                    float ws = sh_w[s0 + sb + i];
                    acc.x = fmaf(ws, pv[i].x, acc.x); acc.y = fmaf(ws, pv[i].y, acc.y);
                    acc.z = fmaf(ws, pv[i].z, acc.z); acc.w = fmaf(ws, pv[i].w, acc.w);
                }
            }
            ((float4*)sp_gx[half])[c] = acc;
        }
        __syncthreads();

        // ---- gates ----
        if (t < 256) {
            const float* gxr = gx + (size_t)(ts * 32 + b) * 768;
            float ghz = sp_gh[0][t]       + sp_gh[1][t];
            float ghr = sp_gh[0][256 + t] + sp_gh[1][256 + t];
            float ghh = sp_gh[0][512 + t] + sp_gh[1][512 + t];
            float gxz = sp_gx[0][t]       + sp_gx[1][t];
            float gxrr= sp_gx[0][256 + t] + sp_gx[1][256 + t];
            float gxh = sp_gx[0][512 + t] + sp_gx[1][512 + t];
            float z  = sigmoidf_(gxr[t]       + gxz + ghz);
            float r  = sigmoidf_(gxr[256 + t] + gxrr + ghr);
            float hh = tanhf(gxr[512 + t] + gxh + r * ghh);
            float hn = z * h_old + (1.f - z) * hh;
            h_old = hn;
            Hdec[(size_t)(b * SSQ + ts) * UU + t] = hn;
            sh_h[cur ^ 1][t] = hn;
        }
        __syncthreads();
    }
}

// ---------------- launch ----------------
extern "C" void kernel_launch(void* const* d_in, const int* in_sizes, int n_in,
                              void* d_out, int out_size) {
    const int*   x         = (const int*)d_in[0];
    const int*   labels    = (const int*)d_in[1];
    const float* enc_embed = (const float*)d_in[2];
    const float* enc_Wx    = (const float*)d_in[3];
    const float* enc_Wh    = (const float*)d_in[4];
    const float* enc_b     = (const float*)d_in[5];
    const float* dec_embed = (const float*)d_in[6];
    const float* dec_Wx    = (const float*)d_in[7];
    const float* dec_Wh    = (const float*)d_in[8];
    const float* dec_b     = (const float*)d_in[9];
    const float* W1        = (const float*)d_in[10];
    const float* b1        = (const float*)d_in[11];
    const float* W2        = (const float*)d_in[12];
    const float* b2        = (const float*)d_in[13];
    const float* Va        = (const float*)d_in[14];
    const float* ba        = (const float*)d_in[15];
    const float* Wfc       = (const float*)d_in[16];
    const float* bfc       = (const float*)d_in[17];
    float* out = (float*)d_out;

    float *gxe, *gxd, *eo, *ep, *Pp, *Hd, *zb;
    __nv_bfloat16 *a2, *b2buf;
    cudaGetSymbolAddress((void**)&gxe, g_gx_enc);
    cudaGetSymbolAddress((void**)&gxd, g_gx_dec);
    cudaGetSymbolAddress((void**)&eo,  g_enc_out);
    cudaGetSymbolAddress((void**)&ep,  g_enc_proj);
    cudaGetSymbolAddress((void**)&Pp,  g_P);
    cudaGetSymbolAddress((void**)&Hd,  g_Hdec);
    cudaGetSymbolAddress((void**)&zb,  g_zb);
    cudaGetSymbolAddress((void**)&a2,  g_A2);
    cudaGetSymbolAddress((void**)&b2buf, g_B2);

    cudaFuncSetAttribute(k_fc_mma, cudaFuncAttributeMaxDynamicSharedMemorySize, 2 * FC_STAGE);

    // 1: both gx GEMMs in one launch
    k_gx_dual<<<dim3(12, 32), 256>>>(enc_embed, enc_Wx, enc_b, gxe,
                                     dec_embed, dec_Wx + 256 * 768, dec_b, gxd, x, labels);
    // 2: encoder recurrence
    k_encoder<<<BB, 512>>>(gxe, enc_Wh, eo);
    // 3: enc_proj + P in one launch
    k_proj_dual<<<dim3(8, 32), 256>>>(eo, W1, b1, ep, dec_Wx, zb, Pp);
    // 4: decoder  <-- profiled launch next round
    k_decoder<<<BB, 512>>>(ep, Pp, gxd, dec_Wh, W2, b2, Va, ba, eo, Hd);
    // 5: Wfc transpose + split
    k_wconv<<<dim3(VV / 64, 4), 256>>>(Wfc, b2buf);
    // 6: Hdec split
    k_hconv<<<512, 512>>>(Hd, a2);
    // 7: FC via HMMA 3-term split
    k_fc_mma<<<dim3(VV / 128, RR / 128), 256, 2 * FC_STAGE>>>(a2, b2buf, bfc, out);
}

// round 12
// speedup vs baseline: 1.1399x; 1.1399x over previous
#include <cuda_runtime.h>
#include <cuda_bf16.h>
#include <math.h>
#include <stdint.h>

#define BB 32
#define SSQ 128
#define EE 256
#define UU 256
#define VV 32000
#define RR (BB*SSQ)   // 4096

// ---------------- device scratch ----------------
__device__ float g_gx_enc[RR * 768];
__device__ float g_gx_dec[RR * 768];
__device__ float g_enc_out[RR * UU];
__device__ float g_enc_proj[RR * UU];
__device__ float g_P[RR * 768];
__device__ float g_Hdec[RR * UU];
__device__ float g_zb[768];                  // zero bias
__device__ __nv_bfloat16 g_A2[(size_t)RR * 512];
__device__ __nv_bfloat16 g_B2[(size_t)VV * 512];

__device__ __forceinline__ float sigmoidf_(float x) { return 1.0f / (1.0f + __expf(-x)); }
__device__ __forceinline__ float tanhapx(float x) {
    float y; asm("tanh.approx.f32 %0, %1;" : "=f"(y) : "f"(x)); return y;
}
__device__ __forceinline__ unsigned smem_u32(const void* p) {
    return (unsigned)__cvta_generic_to_shared(p);
}
#define CP_ASYNC16(saddr, gptr) \
    asm volatile("cp.async.ca.shared.global [%0], [%1], 16;" :: "r"(saddr), "l"(gptr))
#define CP_COMMIT()  asm volatile("cp.async.commit_group;")
#define CP_WAIT0()   asm volatile("cp.async.wait_group 0;")

#define MMA_BF16(c0, c1, c2, c3, a0, a1, a2, a3, b0, b1) \
    asm volatile("mma.sync.aligned.m16n8k16.row.col.f32.bf16.bf16.f32 " \
                 "{%0,%1,%2,%3}, {%4,%5,%6,%7}, {%8,%9}, {%0,%1,%2,%3};" \
                 : "+f"(c0), "+f"(c1), "+f"(c2), "+f"(c3) \
                 : "r"(a0), "r"(a1), "r"(a2), "r"(a3), "r"(b0), "r"(b1))

// ---------------- Wfc transpose + bf16 hi/lo split ----------------
__global__ __launch_bounds__(256)
void k_wconv(const float* __restrict__ W, __nv_bfloat16* __restrict__ B2) {
    __shared__ float tile[64][65];
    const int n0 = blockIdx.x * 64, k0 = blockIdx.y * 64;
    for (int i = threadIdx.x; i < 4096; i += 256) {
        int r = i >> 6, c = i & 63;
        tile[r][c] = W[(size_t)(k0 + r) * VV + n0 + c];
    }
    __syncthreads();
    for (int i = threadIdx.x; i < 4096; i += 256) {
        int r = i >> 6, c = i & 63;
        float v = tile[c][r];
        __nv_bfloat16 h = __float2bfloat16(v);
        __nv_bfloat16 l = __float2bfloat16(v - __bfloat162float(h));
        size_t base = (size_t)(n0 + r) * 512 + k0 + c;
        B2[base] = h;
        B2[base + 256] = l;
    }
}

// ---------------- Hdec -> A2 hi|lo ----------------
__global__ __launch_bounds__(512)
void k_hconv(const float* __restrict__ H, __nv_bfloat16* __restrict__ A2) {
    int i = (blockIdx.x * 512 + threadIdx.x) * 4;
    int row = i >> 8, k = i & 255;
    float4 v = *(const float4*)(H + i);
    __nv_bfloat16 h0 = __float2bfloat16(v.x), h1 = __float2bfloat16(v.y);
    __nv_bfloat16 h2 = __float2bfloat16(v.z), h3 = __float2bfloat16(v.w);
    __nv_bfloat16 l0 = __float2bfloat16(v.x - __bfloat162float(h0));
    __nv_bfloat16 l1 = __float2bfloat16(v.y - __bfloat162float(h1));
    __nv_bfloat16 l2 = __float2bfloat16(v.z - __bfloat162float(h2));
    __nv_bfloat16 l3 = __float2bfloat16(v.w - __bfloat162float(h3));
    __nv_bfloat162 ph0 = __halves2bfloat162(h0, h1), ph1 = __halves2bfloat162(h2, h3);
    __nv_bfloat162 pl0 = __halves2bfloat162(l0, l1), pl1 = __halves2bfloat162(l2, l3);
    size_t base = (size_t)row * 512 + k;
    *(uint2*)(A2 + base)       = make_uint2(*(uint32_t*)&ph0, *(uint32_t*)&ph1);
    *(uint2*)(A2 + base + 256) = make_uint2(*(uint32_t*)&pl0, *(uint32_t*)&pl1);
}

// ---------------- FC via HMMA 3-term split ----------------
#define FCP 144
#define FC_A_BYTES (128 * FCP)
#define FC_STAGE   (2 * FC_A_BYTES)

__device__ __forceinline__ void fc_load(char* sbase, const char* Ag, const char* Bg,
                                        int ca, int cb, int t) {
    const int ar = t >> 1, ac0 = (t & 1) * 4;
#pragma unroll
    for (int i = 0; i < 4; i++) {
        const int col16 = ac0 + i;
        const uint32_t off = (uint32_t)(ar * FCP + col16 * 16);
        CP_ASYNC16(smem_u32(sbase + off),              Ag + (size_t)ar * 1024 + ca * 128 + col16 * 16);
        CP_ASYNC16(smem_u32(sbase + FC_A_BYTES + off), Bg + (size_t)ar * 1024 + cb * 128 + col16 * 16);
    }
}

__global__ __launch_bounds__(256, 2)
void k_fc_mma(const __nv_bfloat16* __restrict__ A2, const __nv_bfloat16* __restrict__ B2,
              const float* __restrict__ bias, float* __restrict__ out) {
    extern __shared__ char smem[];
    const int t = threadIdx.x, lane = t & 31, wid = t >> 5;
    const int bm = blockIdx.y * 128, bn = blockIdx.x * 128;
    const int wm = wid & 3, wn = wid >> 2;
    const int qr = lane >> 2;
    const int qc = (lane & 3) * 2;

    const char* Ag = (const char*)(A2 + (size_t)bm * 512);
    const char* Bg = (const char*)(B2 + (size_t)bn * 512);

    float acc[2][8][4];
#pragma unroll
    for (int mf = 0; mf < 2; mf++)
#pragma unroll
        for (int nf = 0; nf < 8; nf++)
#pragma unroll
            for (int j = 0; j < 4; j++) acc[mf][nf][j] = 0.f;

    fc_load(smem, Ag, Bg, 0, 0, t);
    CP_COMMIT(); CP_WAIT0();
    __syncthreads();

    for (int c = 0; c < 12; c++) {
        const int buf = c & 1;
        if (c < 11) {
            const int p = c + 1, g = p >> 2, j = p & 3;
            fc_load(smem + (buf ^ 1) * FC_STAGE, Ag, Bg,
                    j + ((g == 2) ? 4 : 0), j + ((g == 1) ? 4 : 0), t);
            CP_COMMIT();
        }
        const char* Ab = smem + buf * FC_STAGE;
        const char* Bb = Ab + FC_A_BYTES;

#pragma unroll
        for (int ks = 0; ks < 4; ks++) {
            const int kb = (ks * 16 + qc) * 2;
            uint32_t a[2][4];
#pragma unroll
            for (int mf = 0; mf < 2; mf++) {
                const char* ap = Ab + (wm * 32 + mf * 16 + qr) * FCP + kb;
                a[mf][0] = *(const uint32_t*)(ap);
                a[mf][1] = *(const uint32_t*)(ap + 8 * FCP);
                a[mf][2] = *(const uint32_t*)(ap + 16);
                a[mf][3] = *(const uint32_t*)(ap + 8 * FCP + 16);
            }
            uint32_t bfr[8][2];
#pragma unroll
            for (int nf = 0; nf < 8; nf++) {
                const char* bp = Bb + (wn * 64 + nf * 8 + qr) * FCP + kb;
                bfr[nf][0] = *(const uint32_t*)(bp);
                bfr[nf][1] = *(const uint32_t*)(bp + 16);
            }
#pragma unroll
            for (int mf = 0; mf < 2; mf++)
#pragma unroll
                for (int nf = 0; nf < 8; nf++)
                    MMA_BF16(acc[mf][nf][0], acc[mf][nf][1], acc[mf][nf][2], acc[mf][nf][3],
                             a[mf][0], a[mf][1], a[mf][2], a[mf][3],
                             bfr[nf][0], bfr[nf][1]);
        }
        if (c < 11) CP_WAIT0();
        __syncthreads();
    }

#pragma unroll
    for (int mf = 0; mf < 2; mf++) {
        const int m0 = bm + wm * 32 + mf * 16 + qr;
#pragma unroll
        for (int nf = 0; nf < 8; nf++) {
            const int n = bn + wn * 64 + nf * 8 + qc;
            const float2 bv = *(const float2*)(bias + n);
            float2 o0, o1;
            o0.x = acc[mf][nf][0] + bv.x; o0.y = acc[mf][nf][1] + bv.y;
            o1.x = acc[mf][nf][2] + bv.x; o1.y = acc[mf][nf][3] + bv.y;
            *(float2*)(out + (size_t)m0 * VV + n) = o0;
            *(float2*)(out + (size_t)(m0 + 8) * VV + n) = o1;
        }
    }
}

// ---------------- fp32 GEMM body (device) ----------------
struct SmemGemm { float As[2][16][128]; float Bs[2][16][128]; };

template<int GATHER>
__device__ __forceinline__
void gemm_body(SmemGemm& sm, const float* __restrict__ A, const float* __restrict__ B,
               const float* __restrict__ bias, float* __restrict__ C,
               int N, int K, const int* __restrict__ toks, int bm, int bn) {
    const int t = threadIdx.x;
    const int arow = t >> 1, ak = (t & 1) * 8;
    const int brow = t >> 5, bcol = (t & 31) * 4;
    const int tm0 = (t >> 4) * 8, tn0 = (t & 15) * 8;

    const float* Abase;
    if (GATHER == 0) {
        Abase = A + (size_t)(bm + arow) * K;
    } else {
        int r = bm + arow, s = r >> 5, b = r & 31;
        int tok;
        if (GATHER == 1) tok = toks[b * SSQ + s];
        else             tok = (s == 0) ? 0 : toks[b * SSQ + s - 1];
        Abase = A + (size_t)tok * K;
    }
    const float* Bbase = B + (size_t)brow * N + bn + bcol;

    float acc[8][8];
#pragma unroll
    for (int i = 0; i < 8; i++)
#pragma unroll
        for (int j = 0; j < 8; j++) acc[i][j] = 0.f;

    float4 av0 = *(const float4*)(Abase + ak);
    float4 av1 = *(const float4*)(Abase + ak + 4);
    CP_ASYNC16(smem_u32(&sm.Bs[0][brow][bcol]), Bbase);
    CP_ASYNC16(smem_u32(&sm.Bs[0][brow + 8][bcol]), Bbase + (size_t)8 * N);
    CP_COMMIT();
    sm.As[0][ak + 0][arow] = av0.x; sm.As[0][ak + 1][arow] = av0.y;
    sm.As[0][ak + 2][arow] = av0.z; sm.As[0][ak + 3][arow] = av0.w;
    sm.As[0][ak + 4][arow] = av1.x; sm.As[0][ak + 5][arow] = av1.y;
    sm.As[0][ak + 6][arow] = av1.z; sm.As[0][ak + 7][arow] = av1.w;
    CP_WAIT0();
    __syncthreads();

    const int NT = K >> 4;
    for (int kt = 0; kt < NT; kt++) {
        const int buf = kt & 1, nxt = buf ^ 1;
        const bool more = (kt + 1 < NT);
        if (more) {
            const float* Ap = Abase + (kt + 1) * 16;
            av0 = *(const float4*)(Ap + ak);
            av1 = *(const float4*)(Ap + ak + 4);
            const float* Bp = Bbase + (size_t)(kt + 1) * 16 * N;
            CP_ASYNC16(smem_u32(&sm.Bs[nxt][brow][bcol]), Bp);
            CP_ASYNC16(smem_u32(&sm.Bs[nxt][brow + 8][bcol]), Bp + (size_t)8 * N);
            CP_COMMIT();
        }
#pragma unroll
        for (int kk = 0; kk < 16; kk++) {
            float a[8], bf[8];
            *(float4*)&a[0]  = *(const float4*)&sm.As[buf][kk][tm0];
            *(float4*)&a[4]  = *(const float4*)&sm.As[buf][kk][tm0 + 4];
            *(float4*)&bf[0] = *(const float4*)&sm.Bs[buf][kk][tn0];
            *(float4*)&bf[4] = *(const float4*)&sm.Bs[buf][kk][tn0 + 4];
#pragma unroll
            for (int i = 0; i < 8; i++)
#pragma unroll
                for (int j = 0; j < 8; j++)
                    acc[i][j] = fmaf(a[i], bf[j], acc[i][j]);
        }
        if (more) {
            sm.As[nxt][ak + 0][arow] = av0.x; sm.As[nxt][ak + 1][arow] = av0.y;
            sm.As[nxt][ak + 2][arow] = av0.z; sm.As[nxt][ak + 3][arow] = av0.w;
            sm.As[nxt][ak + 4][arow] = av1.x; sm.As[nxt][ak + 5][arow] = av1.y;
            sm.As[nxt][ak + 6][arow] = av1.z; sm.As[nxt][ak + 7][arow] = av1.w;
            CP_WAIT0();
        }
        __syncthreads();
    }

#pragma unroll
    for (int i = 0; i < 8; i++) {
        float* Crow = C + (size_t)(bm + tm0 + i) * N + bn + tn0;
#pragma unroll
        for (int j = 0; j < 8; j += 4) {
            float4 o;
            o.x = acc[i][j + 0] + bias[bn + tn0 + j + 0];
            o.y = acc[i][j + 1] + bias[bn + tn0 + j + 1];
            o.z = acc[i][j + 2] + bias[bn + tn0 + j + 2];
            o.w = acc[i][j + 3] + bias[bn + tn0 + j + 3];
            *(float4*)(Crow + j) = o;
        }
    }
}

// dual-GEMM 1: gx_enc (blocks x<6) + gx_dec (blocks x>=6)
__global__ __launch_bounds__(256, 2)
void k_gx_dual(const float* __restrict__ enc_embed, const float* __restrict__ enc_Wx,
               const float* __restrict__ enc_b, float* __restrict__ gxe,
               const float* __restrict__ dec_embed, const float* __restrict__ dec_WxE,
               const float* __restrict__ dec_b, float* __restrict__ gxd,
               const int* __restrict__ x, const int* __restrict__ labels) {
    __shared__ SmemGemm sm;
    const int bm = blockIdx.y * 128;
    if (blockIdx.x < 6)
        gemm_body<1>(sm, enc_embed, enc_Wx, enc_b, gxe, 768, 256, x, bm, blockIdx.x * 128);
    else
        gemm_body<2>(sm, dec_embed, dec_WxE, dec_b, gxd, 768, 256, labels, bm, (blockIdx.x - 6) * 128);
}

// dual-GEMM 2: enc_proj (blocks x<2) + P (blocks x>=2)
__global__ __launch_bounds__(256, 2)
void k_proj_dual(const float* __restrict__ eo,
                 const float* __restrict__ W1, const float* __restrict__ b1, float* __restrict__ ep,
                 const float* __restrict__ dec_Wx, const float* __restrict__ zb, float* __restrict__ P) {
    __shared__ SmemGemm sm;
    const int bm = blockIdx.y * 128;
    if (blockIdx.x < 2)
        gemm_body<0>(sm, eo, W1, b1, ep, 256, 256, nullptr, bm, blockIdx.x * 128);
    else
        gemm_body<0>(sm, eo, dec_Wx, zb, P, 768, 256, nullptr, bm, (blockIdx.x - 2) * 128);
}

// ---------------- encoder GRU: 16-deep register staging (best-known config) ----------------
__global__ __launch_bounds__(512)
void k_encoder(const float* __restrict__ gx, const float* __restrict__ Wh,
               float* __restrict__ enc_out) {
    __shared__ float sh_h[2][UU];
    __shared__ float sp[2][768];
    const int b = blockIdx.x, t = threadIdx.x;
    float h_old = 0.f;
    if (t < 256) sh_h[0][t] = 0.f;
    __syncthreads();
    for (int s = 0; s < SSQ; s++) {
        const int cur = s & 1;
        if (t < 384) {
            const int half = (t >= 192), c = t - half * 192;
            const float4* W4 = (const float4*)Wh + c;
            float4 acc = make_float4(0.f, 0.f, 0.f, 0.f);
            const int k0 = half * 128;
            for (int kb = 0; kb < 128; kb += 16) {
                float4 wv[16];
#pragma unroll
                for (int i = 0; i < 16; i++) wv[i] = W4[(size_t)(k0 + kb + i) * 192];
#pragma unroll
                for (int i = 0; i < 16; i++) {
                    float hk = sh_h[cur][k0 + kb + i];
                    acc.x = fmaf(hk, wv[i].x, acc.x); acc.y = fmaf(hk, wv[i].y, acc.y);
                    acc.z = fmaf(hk, wv[i].z, acc.z); acc.w = fmaf(hk, wv[i].w, acc.w);
                }
            }
            ((float4*)sp[half])[c] = acc;
        }
        __syncthreads();
        if (t < 256) {
            const float* gxr = gx + (size_t)(s * 32 + b) * 768;
            float z  = sigmoidf_(gxr[t]       + sp[0][t]       + sp[1][t]);
            float r  = sigmoidf_(gxr[256 + t] + sp[0][256 + t] + sp[1][256 + t]);
            float hh = tanhf(gxr[512 + t] + r * (sp[0][512 + t] + sp[1][512 + t]));
            float hn = z * h_old + (1.f - z) * hh;
            h_old = hn;
            enc_out[(size_t)(b * SSQ + s) * UU + t] = hn;
            sh_h[cur ^ 1][t] = hn;
        }
        __syncthreads();
    }
}

// ---------------- decoder: 16-deep staging (best-known config) ----------------
__global__ __launch_bounds__(512)
void k_decoder(const float* __restrict__ enc_proj, const float* __restrict__ P,
               const float* __restrict__ gx, const float* __restrict__ dec_Wh,
               const float* __restrict__ W2, const float* __restrict__ b2,
               const float* __restrict__ Va, const float* __restrict__ ba,
               const float* __restrict__ enc_out, float* __restrict__ Hdec) {
    __shared__ float sh_h[2][UU];
    __shared__ float sh_Va[UU];
    __shared__ float sh_sc[SSQ];
    __shared__ float sh_w[SSQ];
    __shared__ float sp_q[2][UU];
    __shared__ float sp_gh[2][768];
    __shared__ float sp_gx[2][768];
    __shared__ float sred[8];

    const int b = blockIdx.x, t = threadIdx.x;
    float h_old = 0.f;
    if (t < 256) {
        sh_Va[t] = Va[t];
        h_old = enc_out[(size_t)(b * SSQ + 127) * UU + t];
        sh_h[0][t] = h_old;
    }
    const float ba0 = ba[0];
    __syncthreads();

    for (int ts = 0; ts < SSQ; ts++) {
        const int cur = ts & 1;
        // ---- Phase A: q = h@W2 (t<128) || gh = h@Wh (t in [128,512)) ----
        if (t < 128) {
            const int c = t & 63, half = t >> 6;
            const float4* W4 = (const float4*)W2 + c;
            float4 acc = make_float4(0.f, 0.f, 0.f, 0.f);
            const int k0 = half * 128;
            for (int kb = 0; kb < 128; kb += 16) {
                float4 wv[16];
#pragma unroll
                for (int i = 0; i < 16; i++) wv[i] = W4[(size_t)(k0 + kb + i) * 64];
#pragma unroll
                for (int i = 0; i < 16; i++) {
                    float hk = sh_h[cur][k0 + kb + i];
                    acc.x = fmaf(hk, wv[i].x, acc.x); acc.y = fmaf(hk, wv[i].y, acc.y);
                    acc.z = fmaf(hk, wv[i].z, acc.z); acc.w = fmaf(hk, wv[i].w, acc.w);
                }
            }
            if (half == 0) {
                float4 bb = ((const float4*)b2)[c];
                acc.x += bb.x; acc.y += bb.y; acc.z += bb.z; acc.w += bb.w;
            }
            ((float4*)sp_q[half])[c] = acc;
        } else {
            const int u = t - 128;
            const int c = u % 192, half = u / 192;
            const float4* Wh4 = (const float4*)dec_Wh + c;
            float4 acc = make_float4(0.f, 0.f, 0.f, 0.f);
            const int k0 = half * 128;
            for (int kb = 0; kb < 128; kb += 16) {
                float4 wv[16];
#pragma unroll
                for (int i = 0; i < 16; i++) wv[i] = Wh4[(size_t)(k0 + kb + i) * 192];
#pragma unroll
                for (int i = 0; i < 16; i++) {
                    float hk = sh_h[cur][k0 + kb + i];
                    acc.x = fmaf(hk, wv[i].x, acc.x); acc.y = fmaf(hk, wv[i].y, acc.y);
                    acc.z = fmaf(hk, wv[i].z, acc.z); acc.w = fmaf(hk, wv[i].w, acc.w);
                }
            }
            ((float4*)sp_gh[half])[c] = acc;
        }
        __syncthreads();

        // ---- attention scores ----
        {
            const int s = t >> 2, qd = t & 3;
            const float4* ep = (const float4*)(enc_proj + (size_t)(b * SSQ + s) * UU) + qd * 16;
            const float4* q0 = (const float4*)sp_q[0] + qd * 16;
            const float4* q1 = (const float4*)sp_q[1] + qd * 16;
            const float4* v4 = (const float4*)sh_Va + qd * 16;
            float acc = 0.f;
#pragma unroll 16
            for (int i = 0; i < 16; i++) {
                float4 p = ep[i], qa = q0[i], qb = q1[i], vv = v4[i];
                acc += tanhapx(p.x + qa.x + qb.x) * vv.x;
                acc += tanhapx(p.y + qa.y + qb.y) * vv.y;
                acc += tanhapx(p.z + qa.z + qb.z) * vv.z;
                acc += tanhapx(p.w + qa.w + qb.w) * vv.w;
            }
            acc += __shfl_xor_sync(0xffffffffu, acc, 1);
            acc += __shfl_xor_sync(0xffffffffu, acc, 2);
            if (qd == 0) sh_sc[s] = acc + ba0;
        }
        __syncthreads();

        // ---- softmax ----
        {
            float v = (t < 128) ? sh_sc[t] : -1e30f;
            float m = v;
#pragma unroll
            for (int o = 16; o; o >>= 1) m = fmaxf(m, __shfl_xor_sync(0xffffffffu, m, o));
            if (t < 128 && (t & 31) == 0) sred[t >> 5] = m;
            __syncthreads();
            float gm = fmaxf(fmaxf(sred[0], sred[1]), fmaxf(sred[2], sred[3]));
            float e = (t < 128) ? __expf(v - gm) : 0.f;
            float ssum = e;
#pragma unroll
            for (int o = 16; o; o >>= 1) ssum += __shfl_xor_sync(0xffffffffu, ssum, o);
            __syncthreads();
            if (t < 128 && (t & 31) == 0) sred[t >> 5] = ssum;
            __syncthreads();
            float gs = sred[0] + sred[1] + sred[2] + sred[3];
            if (t < 128) sh_w[t] = e / gs;
        }
        __syncthreads();

        // ---- gxP = sum_s w[s] * P[b,s,:] ----
        if (t < 384) {
            const int half = (t >= 192), c = t - half * 192;
            const float4* P4 = (const float4*)(P + (size_t)(b * SSQ) * 768) + c;
            float4 acc = make_float4(0.f, 0.f, 0.f, 0.f);
            const int s0 = half * 64;
            for (int sb = 0; sb < 64; sb += 16) {
                float4 pv[16];
#pragma unroll
                for (int i = 0; i < 16; i++) pv[i] = P4[(size_t)(s0 + sb + i) * 192];
#pragma unroll
                for (int i = 0; i < 16; i++) {
                    float ws = sh_w[s0 + sb + i];
                    acc.x = fmaf(ws, pv[i].x, acc.x); acc.y = fmaf(ws, pv[i].y, acc.y);
                    acc.z = fmaf(ws, pv[i].z, acc.z); acc.w = fmaf(ws, pv[i].w, acc.w);
                }
            }
            ((float4*)sp_gx[half])[c] = acc;
        }
        __syncthreads();

        // ---- gates ----
        if (t < 256) {
            const float* gxr = gx + (size_t)(ts * 32 + b) * 768;
            float ghz = sp_gh[0][t]       + sp_gh[1][t];
            float ghr = sp_gh[0][256 + t] + sp_gh[1][256 + t];
            float ghh = sp_gh[0][512 + t] + sp_gh[1][512 + t];
            float gxz = sp_gx[0][t]       + sp_gx[1][t];
            float gxrr= sp_gx[0][256 + t] + sp_gx[1][256 + t];
            float gxh = sp_gx[0][512 + t] + sp_gx[1][512 + t];
            float z  = sigmoidf_(gxr[t]       + gxz + ghz);
            float r  = sigmoidf_(gxr[256 + t] + gxrr + ghr);
            float hh = tanhf(gxr[512 + t] + gxh + r * ghh);
            float hn = z * h_old + (1.f - z) * hh;
            h_old = hn;
            Hdec[(size_t)(b * SSQ + ts) * UU + t] = hn;
            sh_h[cur ^ 1][t] = hn;
        }
        __syncthreads();
    }
}

// ---------------- launch ----------------
extern "C" void kernel_launch(void* const* d_in, const int* in_sizes, int n_in,
                              void* d_out, int out_size) {
    const int*   x         = (const int*)d_in[0];
    const int*   labels    = (const int*)d_in[1];
    const float* enc_embed = (const float*)d_in[2];
    const float* enc_Wx    = (const float*)d_in[3];
    const float* enc_Wh    = (const float*)d_in[4];
    const float* enc_b     = (const float*)d_in[5];
    const float* dec_embed = (const float*)d_in[6];
    const float* dec_Wx    = (const float*)d_in[7];
    const float* dec_Wh    = (const float*)d_in[8];
    const float* dec_b     = (const float*)d_in[9];
    const float* W1        = (const float*)d_in[10];
    const float* b1        = (const float*)d_in[11];
    const float* W2        = (const float*)d_in[12];
    const float* b2        = (const float*)d_in[13];
    const float* Va        = (const float*)d_in[14];
    const float* ba        = (const float*)d_in[15];
    const float* Wfc       = (const float*)d_in[16];
    const float* bfc       = (const float*)d_in[17];
    float* out = (float*)d_out;

    float *gxe, *gxd, *eo, *ep, *Pp, *Hd, *zb;
    __nv_bfloat16 *a2, *b2buf;
    cudaGetSymbolAddress((void**)&gxe, g_gx_enc);
    cudaGetSymbolAddress((void**)&gxd, g_gx_dec);
    cudaGetSymbolAddress((void**)&eo,  g_enc_out);
    cudaGetSymbolAddress((void**)&ep,  g_enc_proj);
    cudaGetSymbolAddress((void**)&Pp,  g_P);
    cudaGetSymbolAddress((void**)&Hd,  g_Hdec);
    cudaGetSymbolAddress((void**)&zb,  g_zb);
    cudaGetSymbolAddress((void**)&a2,  g_A2);
    cudaGetSymbolAddress((void**)&b2buf, g_B2);

    cudaFuncSetAttribute(k_fc_mma, cudaFuncAttributeMaxDynamicSharedMemorySize, 2 * FC_STAGE);

    // 1: both gx GEMMs in one launch
    k_gx_dual<<<dim3(12, 32), 256>>>(enc_embed, enc_Wx, enc_b, gxe,
                                     dec_embed, dec_Wx + 256 * 768, dec_b, gxd, x, labels);
    // 2: encoder recurrence
    k_encoder<<<BB, 512>>>(gxe, enc_Wh, eo);
    // 3: enc_proj + P in one launch
    k_proj_dual<<<dim3(8, 32), 256>>>(eo, W1, b1, ep, dec_Wx, zb, Pp);
    // 4: decoder  <-- profiled launch
    k_decoder<<<BB, 512>>>(ep, Pp, gxd, dec_Wh, W2, b2, Va, ba, eo, Hd);
    // 5: Wfc transpose + split
    k_wconv<<<dim3(VV / 64, 4), 256>>>(Wfc, b2buf);
    // 6: Hdec split
    k_hconv<<<512, 512>>>(Hd, a2);
    // 7: FC via HMMA 3-term split
    k_fc_mma<<<dim3(VV / 128, RR / 128), 256, 2 * FC_STAGE>>>(a2, b2buf, bfc, out);
}

// round 13
// speedup vs baseline: 1.3694x; 1.2013x over previous
#include <cuda_runtime.h>
#include <cuda_bf16.h>
#include <math.h>
#include <stdint.h>

#define BB 32
#define SSQ 128
#define EE 256
#define UU 256
#define VV 32000
#define RR (BB*SSQ)   // 4096

// ---------------- device scratch ----------------
__device__ float g_gx_enc[RR * 768];
__device__ float g_gx_dec[RR * 768];
__device__ float g_enc_out[RR * UU];
__device__ float g_enc_proj[RR * UU];
__device__ float g_P[RR * 768];
__device__ float g_Hdec[RR * UU];
__device__ float g_zb[768];                  // zero bias
__device__ __nv_bfloat16 g_A2[(size_t)RR * 512];
__device__ __nv_bfloat16 g_B2[(size_t)VV * 512];

__device__ __forceinline__ float sigmoidf_(float x) { return 1.0f / (1.0f + __expf(-x)); }
__device__ __forceinline__ float tanhapx(float x) {
    float y; asm("tanh.approx.f32 %0, %1;" : "=f"(y) : "f"(x)); return y;
}
__device__ __forceinline__ unsigned smem_u32(const void* p) {
    return (unsigned)__cvta_generic_to_shared(p);
}
#define CP_ASYNC16(saddr, gptr) \
    asm volatile("cp.async.ca.shared.global [%0], [%1], 16;" :: "r"(saddr), "l"(gptr))
#define CP_COMMIT()  asm volatile("cp.async.commit_group;")
#define CP_WAIT0()   asm volatile("cp.async.wait_group 0;")

#define MMA_BF16(c0, c1, c2, c3, a0, a1, a2, a3, b0, b1) \
    asm volatile("mma.sync.aligned.m16n8k16.row.col.f32.bf16.bf16.f32 " \
                 "{%0,%1,%2,%3}, {%4,%5,%6,%7}, {%8,%9}, {%0,%1,%2,%3};" \
                 : "+f"(c0), "+f"(c1), "+f"(c2), "+f"(c3) \
                 : "r"(a0), "r"(a1), "r"(a2), "r"(a3), "r"(b0), "r"(b1))

// ---------------- Wfc transpose + bf16 hi/lo split ----------------
__global__ __launch_bounds__(256)
void k_wconv(const float* __restrict__ W, __nv_bfloat16* __restrict__ B2) {
    __shared__ float tile[64][65];
    const int n0 = blockIdx.x * 64, k0 = blockIdx.y * 64;
    for (int i = threadIdx.x; i < 4096; i += 256) {
        int r = i >> 6, c = i & 63;
        tile[r][c] = W[(size_t)(k0 + r) * VV + n0 + c];
    }
    __syncthreads();
    for (int i = threadIdx.x; i < 4096; i += 256) {
        int r = i >> 6, c = i & 63;
        float v = tile[c][r];
        __nv_bfloat16 h = __float2bfloat16(v);
        __nv_bfloat16 l = __float2bfloat16(v - __bfloat162float(h));
        size_t base = (size_t)(n0 + r) * 512 + k0 + c;
        B2[base] = h;
        B2[base + 256] = l;
    }
}

// ---------------- Hdec -> A2 hi|lo ----------------
__global__ __launch_bounds__(512)
void k_hconv(const float* __restrict__ H, __nv_bfloat16* __restrict__ A2) {
    int i = (blockIdx.x * 512 + threadIdx.x) * 4;
    int row = i >> 8, k = i & 255;
    float4 v = *(const float4*)(H + i);
    __nv_bfloat16 h0 = __float2bfloat16(v.x), h1 = __float2bfloat16(v.y);
    __nv_bfloat16 h2 = __float2bfloat16(v.z), h3 = __float2bfloat16(v.w);
    __nv_bfloat16 l0 = __float2bfloat16(v.x - __bfloat162float(h0));
    __nv_bfloat16 l1 = __float2bfloat16(v.y - __bfloat162float(h1));
    __nv_bfloat16 l2 = __float2bfloat16(v.z - __bfloat162float(h2));
    __nv_bfloat16 l3 = __float2bfloat16(v.w - __bfloat162float(h3));
    __nv_bfloat162 ph0 = __halves2bfloat162(h0, h1), ph1 = __halves2bfloat162(h2, h3);
    __nv_bfloat162 pl0 = __halves2bfloat162(l0, l1), pl1 = __halves2bfloat162(l2, l3);
    size_t base = (size_t)row * 512 + k;
    *(uint2*)(A2 + base)       = make_uint2(*(uint32_t*)&ph0, *(uint32_t*)&ph1);
    *(uint2*)(A2 + base + 256) = make_uint2(*(uint32_t*)&pl0, *(uint32_t*)&pl1);
}

// ---------------- FC via HMMA 3-term split ----------------
#define FCP 144
#define FC_A_BYTES (128 * FCP)
#define FC_STAGE   (2 * FC_A_BYTES)

__device__ __forceinline__ void fc_load(char* sbase, const char* Ag, const char* Bg,
                                        int ca, int cb, int t) {
    const int ar = t >> 1, ac0 = (t & 1) * 4;
#pragma unroll
    for (int i = 0; i < 4; i++) {
        const int col16 = ac0 + i;
        const uint32_t off = (uint32_t)(ar * FCP + col16 * 16);
        CP_ASYNC16(smem_u32(sbase + off),              Ag + (size_t)ar * 1024 + ca * 128 + col16 * 16);
        CP_ASYNC16(smem_u32(sbase + FC_A_BYTES + off), Bg + (size_t)ar * 1024 + cb * 128 + col16 * 16);
    }
}

__global__ __launch_bounds__(256, 2)
void k_fc_mma(const __nv_bfloat16* __restrict__ A2, const __nv_bfloat16* __restrict__ B2,
              const float* __restrict__ bias, float* __restrict__ out) {
    extern __shared__ char smem[];
    const int t = threadIdx.x, lane = t & 31, wid = t >> 5;
    const int bm = blockIdx.y * 128, bn = blockIdx.x * 128;
    const int wm = wid & 3, wn = wid >> 2;
    const int qr = lane >> 2;
    const int qc = (lane & 3) * 2;

    const char* Ag = (const char*)(A2 + (size_t)bm * 512);
    const char* Bg = (const char*)(B2 + (size_t)bn * 512);

    float acc[2][8][4];
#pragma unroll
    for (int mf = 0; mf < 2; mf++)
#pragma unroll
        for (int nf = 0; nf < 8; nf++)
#pragma unroll
            for (int j = 0; j < 4; j++) acc[mf][nf][j] = 0.f;

    fc_load(smem, Ag, Bg, 0, 0, t);
    CP_COMMIT(); CP_WAIT0();
    __syncthreads();

    for (int c = 0; c < 12; c++) {
        const int buf = c & 1;
        if (c < 11) {
            const int p = c + 1, g = p >> 2, j = p & 3;
            fc_load(smem + (buf ^ 1) * FC_STAGE, Ag, Bg,
                    j + ((g == 2) ? 4 : 0), j + ((g == 1) ? 4 : 0), t);
            CP_COMMIT();
        }
        const char* Ab = smem + buf * FC_STAGE;
        const char* Bb = Ab + FC_A_BYTES;

#pragma unroll
        for (int ks = 0; ks < 4; ks++) {
            const int kb = (ks * 16 + qc) * 2;
            uint32_t a[2][4];
#pragma unroll
            for (int mf = 0; mf < 2; mf++) {
                const char* ap = Ab + (wm * 32 + mf * 16 + qr) * FCP + kb;
                a[mf][0] = *(const uint32_t*)(ap);
                a[mf][1] = *(const uint32_t*)(ap + 8 * FCP);
                a[mf][2] = *(const uint32_t*)(ap + 16);
                a[mf][3] = *(const uint32_t*)(ap + 8 * FCP + 16);
            }
            uint32_t bfr[8][2];
#pragma unroll
            for (int nf = 0; nf < 8; nf++) {
                const char* bp = Bb + (wn * 64 + nf * 8 + qr) * FCP + kb;
                bfr[nf][0] = *(const uint32_t*)(bp);
                bfr[nf][1] = *(const uint32_t*)(bp + 16);
            }
#pragma unroll
            for (int mf = 0; mf < 2; mf++)
#pragma unroll
                for (int nf = 0; nf < 8; nf++)
                    MMA_BF16(acc[mf][nf][0], acc[mf][nf][1], acc[mf][nf][2], acc[mf][nf][3],
                             a[mf][0], a[mf][1], a[mf][2], a[mf][3],
                             bfr[nf][0], bfr[nf][1]);
        }
        if (c < 11) CP_WAIT0();
        __syncthreads();
    }

#pragma unroll
    for (int mf = 0; mf < 2; mf++) {
        const int m0 = bm + wm * 32 + mf * 16 + qr;
#pragma unroll
        for (int nf = 0; nf < 8; nf++) {
            const int n = bn + wn * 64 + nf * 8 + qc;
            const float2 bv = *(const float2*)(bias + n);
            float2 o0, o1;
            o0.x = acc[mf][nf][0] + bv.x; o0.y = acc[mf][nf][1] + bv.y;
            o1.x = acc[mf][nf][2] + bv.x; o1.y = acc[mf][nf][3] + bv.y;
            *(float2*)(out + (size_t)m0 * VV + n) = o0;
            *(float2*)(out + (size_t)(m0 + 8) * VV + n) = o1;
        }
    }
}

// ---------------- fp32 GEMM body (device) ----------------
struct SmemGemm { float As[2][16][128]; float Bs[2][16][128]; };

template<int GATHER>
__device__ __forceinline__
void gemm_body(SmemGemm& sm, const float* __restrict__ A, const float* __restrict__ B,
               const float* __restrict__ bias, float* __restrict__ C,
               int N, int K, const int* __restrict__ toks, int bm, int bn) {
    const int t = threadIdx.x;
    const int arow = t >> 1, ak = (t & 1) * 8;
    const int brow = t >> 5, bcol = (t & 31) * 4;
    const int tm0 = (t >> 4) * 8, tn0 = (t & 15) * 8;

    const float* Abase;
    if (GATHER == 0) {
        Abase = A + (size_t)(bm + arow) * K;
    } else {
        int r = bm + arow, s = r >> 5, b = r & 31;
        int tok;
        if (GATHER == 1) tok = toks[b * SSQ + s];
        else             tok = (s == 0) ? 0 : toks[b * SSQ + s - 1];
        Abase = A + (size_t)tok * K;
    }
    const float* Bbase = B + (size_t)brow * N + bn + bcol;

    float acc[8][8];
#pragma unroll
    for (int i = 0; i < 8; i++)
#pragma unroll
        for (int j = 0; j < 8; j++) acc[i][j] = 0.f;

    float4 av0 = *(const float4*)(Abase + ak);
    float4 av1 = *(const float4*)(Abase + ak + 4);
    CP_ASYNC16(smem_u32(&sm.Bs[0][brow][bcol]), Bbase);
    CP_ASYNC16(smem_u32(&sm.Bs[0][brow + 8][bcol]), Bbase + (size_t)8 * N);
    CP_COMMIT();
    sm.As[0][ak + 0][arow] = av0.x; sm.As[0][ak + 1][arow] = av0.y;
    sm.As[0][ak + 2][arow] = av0.z; sm.As[0][ak + 3][arow] = av0.w;
    sm.As[0][ak + 4][arow] = av1.x; sm.As[0][ak + 5][arow] = av1.y;
    sm.As[0][ak + 6][arow] = av1.z; sm.As[0][ak + 7][arow] = av1.w;
    CP_WAIT0();
    __syncthreads();

    const int NT = K >> 4;
    for (int kt = 0; kt < NT; kt++) {
        const int buf = kt & 1, nxt = buf ^ 1;
        const bool more = (kt + 1 < NT);
        if (more) {
            const float* Ap = Abase + (kt + 1) * 16;
            av0 = *(const float4*)(Ap + ak);
            av1 = *(const float4*)(Ap + ak + 4);
            const float* Bp = Bbase + (size_t)(kt + 1) * 16 * N;
            CP_ASYNC16(smem_u32(&sm.Bs[nxt][brow][bcol]), Bp);
            CP_ASYNC16(smem_u32(&sm.Bs[nxt][brow + 8][bcol]), Bp + (size_t)8 * N);
            CP_COMMIT();
        }
#pragma unroll
        for (int kk = 0; kk < 16; kk++) {
            float a[8], bf[8];
            *(float4*)&a[0]  = *(const float4*)&sm.As[buf][kk][tm0];
            *(float4*)&a[4]  = *(const float4*)&sm.As[buf][kk][tm0 + 4];
            *(float4*)&bf[0] = *(const float4*)&sm.Bs[buf][kk][tn0];
            *(float4*)&bf[4] = *(const float4*)&sm.Bs[buf][kk][tn0 + 4];
#pragma unroll
            for (int i = 0; i < 8; i++)
#pragma unroll
                for (int j = 0; j < 8; j++)
                    acc[i][j] = fmaf(a[i], bf[j], acc[i][j]);
        }
        if (more) {
            sm.As[nxt][ak + 0][arow] = av0.x; sm.As[nxt][ak + 1][arow] = av0.y;
            sm.As[nxt][ak + 2][arow] = av0.z; sm.As[nxt][ak + 3][arow] = av0.w;
            sm.As[nxt][ak + 4][arow] = av1.x; sm.As[nxt][ak + 5][arow] = av1.y;
            sm.As[nxt][ak + 6][arow] = av1.z; sm.As[nxt][ak + 7][arow] = av1.w;
            CP_WAIT0();
        }
        __syncthreads();
    }

#pragma unroll
    for (int i = 0; i < 8; i++) {
        float* Crow = C + (size_t)(bm + tm0 + i) * N + bn + tn0;
#pragma unroll
        for (int j = 0; j < 8; j += 4) {
            float4 o;
            o.x = acc[i][j + 0] + bias[bn + tn0 + j + 0];
            o.y = acc[i][j + 1] + bias[bn + tn0 + j + 1];
            o.z = acc[i][j + 2] + bias[bn + tn0 + j + 2];
            o.w = acc[i][j + 3] + bias[bn + tn0 + j + 3];
            *(float4*)(Crow + j) = o;
        }
    }
}

// dual-GEMM 1: gx_enc (blocks x<6) + gx_dec (blocks x>=6)
__global__ __launch_bounds__(256, 2)
void k_gx_dual(const float* __restrict__ enc_embed, const float* __restrict__ enc_Wx,
               const float* __restrict__ enc_b, float* __restrict__ gxe,
               const float* __restrict__ dec_embed, const float* __restrict__ dec_WxE,
               const float* __restrict__ dec_b, float* __restrict__ gxd,
               const int* __restrict__ x, const int* __restrict__ labels) {
    __shared__ SmemGemm sm;
    const int bm = blockIdx.y * 128;
    if (blockIdx.x < 6)
        gemm_body<1>(sm, enc_embed, enc_Wx, enc_b, gxe, 768, 256, x, bm, blockIdx.x * 128);
    else
        gemm_body<2>(sm, dec_embed, dec_WxE, dec_b, gxd, 768, 256, labels, bm, (blockIdx.x - 6) * 128);
}

// dual-GEMM 2: enc_proj (blocks x<2) + P (blocks x>=2)
__global__ __launch_bounds__(256, 2)
void k_proj_dual(const float* __restrict__ eo,
                 const float* __restrict__ W1, const float* __restrict__ b1, float* __restrict__ ep,
                 const float* __restrict__ dec_Wx, const float* __restrict__ zb, float* __restrict__ P) {
    __shared__ SmemGemm sm;
    const int bm = blockIdx.y * 128;
    if (blockIdx.x < 2)
        gemm_body<0>(sm, eo, W1, b1, ep, 256, 256, nullptr, bm, blockIdx.x * 128);
    else
        gemm_body<0>(sm, eo, dec_Wx, zb, P, 768, 256, nullptr, bm, (blockIdx.x - 2) * 128);
}

// ---------------- encoder GRU: 1024 threads, 4-way k-split (64 iters) ----------------
__global__ __launch_bounds__(1024)
void k_encoder(const float* __restrict__ gx, const float* __restrict__ Wh,
               float* __restrict__ enc_out) {
    __shared__ float sh_h[2][UU];
    __shared__ float sp[4][768];
    const int b = blockIdx.x, t = threadIdx.x;
    float h_old = 0.f;
    if (t < 256) sh_h[0][t] = 0.f;
    __syncthreads();
    for (int s = 0; s < SSQ; s++) {
        const int cur = s & 1;
        if (t < 768) {
            const int c = t % 192, quarter = t / 192;
            const float4* W4 = (const float4*)Wh + c;
            float4 acc = make_float4(0.f, 0.f, 0.f, 0.f);
            const int k0 = quarter * 64;
            for (int kb = 0; kb < 64; kb += 16) {
                float4 wv[16];
#pragma unroll
                for (int i = 0; i < 16; i++) wv[i] = W4[(size_t)(k0 + kb + i) * 192];
#pragma unroll
                for (int i = 0; i < 16; i++) {
                    float hk = sh_h[cur][k0 + kb + i];
                    acc.x = fmaf(hk, wv[i].x, acc.x); acc.y = fmaf(hk, wv[i].y, acc.y);
                    acc.z = fmaf(hk, wv[i].z, acc.z); acc.w = fmaf(hk, wv[i].w, acc.w);
                }
            }
            ((float4*)sp[quarter])[c] = acc;
        }
        __syncthreads();
        if (t < 256) {
            const float* gxr = gx + (size_t)(s * 32 + b) * 768;
            float ghz = sp[0][t]       + sp[1][t]       + sp[2][t]       + sp[3][t];
            float ghr = sp[0][256 + t] + sp[1][256 + t] + sp[2][256 + t] + sp[3][256 + t];
            float ghh = sp[0][512 + t] + sp[1][512 + t] + sp[2][512 + t] + sp[3][512 + t];
            float z  = sigmoidf_(gxr[t]       + ghz);
            float r  = sigmoidf_(gxr[256 + t] + ghr);
            float hh = tanhf(gxr[512 + t] + r * ghh);
            float hn = z * h_old + (1.f - z) * hh;
            h_old = hn;
            enc_out[(size_t)(b * SSQ + s) * UU + t] = hn;
            sh_h[cur ^ 1][t] = hn;
        }
        __syncthreads();
    }
}

// ---------------- decoder: 1024 threads, 4-way splits, warp0 softmax ----------------
__global__ __launch_bounds__(1024)
void k_decoder(const float* __restrict__ enc_proj, const float* __restrict__ P,
               const float* __restrict__ gx, const float* __restrict__ dec_Wh,
               const float* __restrict__ W2, const float* __restrict__ b2,
               const float* __restrict__ Va, const float* __restrict__ ba,
               const float* __restrict__ enc_out, float* __restrict__ Hdec) {
    __shared__ float sh_h[2][UU];
    __shared__ float sh_q[UU];
    __shared__ float sh_Va[UU];
    __shared__ float sh_sc[SSQ];
    __shared__ float sh_w[SSQ];
    __shared__ float sp_q[4][UU];
    __shared__ float sp_gh[4][768];
    __shared__ float sp_gx[4][768];

    const int b = blockIdx.x, t = threadIdx.x;
    float h_old = 0.f;
    if (t < 256) {
        sh_Va[t] = Va[t];
        h_old = enc_out[(size_t)(b * SSQ + 127) * UU + t];
        sh_h[0][t] = h_old;
    }
    const float ba0 = ba[0];
    __syncthreads();

    for (int ts = 0; ts < SSQ; ts++) {
        const int cur = ts & 1;
        // ---- Phase A: q (t<256, 4-way k) || gh (t in [256,1024), 4-way k) ----
        if (t < 256) {
            const int c = t & 63, quarter = t >> 6;
            const float4* W4 = (const float4*)W2 + c;
            float4 acc = make_float4(0.f, 0.f, 0.f, 0.f);
            const int k0 = quarter * 64;
            for (int kb = 0; kb < 64; kb += 16) {
                float4 wv[16];
#pragma unroll
                for (int i = 0; i < 16; i++) wv[i] = W4[(size_t)(k0 + kb + i) * 64];
#pragma unroll
                for (int i = 0; i < 16; i++) {
                    float hk = sh_h[cur][k0 + kb + i];
                    acc.x = fmaf(hk, wv[i].x, acc.x); acc.y = fmaf(hk, wv[i].y, acc.y);
                    acc.z = fmaf(hk, wv[i].z, acc.z); acc.w = fmaf(hk, wv[i].w, acc.w);
                }
            }
            if (quarter == 0) {
                float4 bb = ((const float4*)b2)[c];
                acc.x += bb.x; acc.y += bb.y; acc.z += bb.z; acc.w += bb.w;
            }
            ((float4*)sp_q[quarter])[c] = acc;
        } else {
            const int u = t - 256;
            const int c = u % 192, quarter = u / 192;
            const float4* Wh4 = (const float4*)dec_Wh + c;
            float4 acc = make_float4(0.f, 0.f, 0.f, 0.f);
            const int k0 = quarter * 64;
            for (int kb = 0; kb < 64; kb += 16) {
                float4 wv[16];
#pragma unroll
                for (int i = 0; i < 16; i++) wv[i] = Wh4[(size_t)(k0 + kb + i) * 192];
#pragma unroll
                for (int i = 0; i < 16; i++) {
                    float hk = sh_h[cur][k0 + kb + i];
                    acc.x = fmaf(hk, wv[i].x, acc.x); acc.y = fmaf(hk, wv[i].y, acc.y);
                    acc.z = fmaf(hk, wv[i].z, acc.z); acc.w = fmaf(hk, wv[i].w, acc.w);
                }
            }
            ((float4*)sp_gh[quarter])[c] = acc;
        }
        __syncthreads();

        // ---- q-sum (64 threads) ----
        if (t < 64) {
            float4 a0 = ((const float4*)sp_q[0])[t];
            float4 a1 = ((const float4*)sp_q[1])[t];
            float4 a2 = ((const float4*)sp_q[2])[t];
            float4 a3 = ((const float4*)sp_q[3])[t];
            float4 o;
            o.x = a0.x + a1.x + a2.x + a3.x;
            o.y = a0.y + a1.y + a2.y + a3.y;
            o.z = a0.z + a1.z + a2.z + a3.z;
            o.w = a0.w + a1.w + a2.w + a3.w;
            ((float4*)sh_q)[t] = o;
        }
        __syncthreads();

        // ---- attention scores (512 threads: 4/s, MUFU floor anyway) ----
        if (t < 512) {
            const int s = t >> 2, qd = t & 3;
            const float4* ep = (const float4*)(enc_proj + (size_t)(b * SSQ + s) * UU) + qd * 16;
            const float4* q4 = (const float4*)sh_q + qd * 16;
            const float4* v4 = (const float4*)sh_Va + qd * 16;
            float acc = 0.f;
#pragma unroll 16
            for (int i = 0; i < 16; i++) {
                float4 p = ep[i], qa = q4[i], vv = v4[i];
                acc += tanhapx(p.x + qa.x) * vv.x;
                acc += tanhapx(p.y + qa.y) * vv.y;
                acc += tanhapx(p.z + qa.z) * vv.z;
                acc += tanhapx(p.w + qa.w) * vv.w;
            }
            acc += __shfl_xor_sync(0xffffffffu, acc, 1);
            acc += __shfl_xor_sync(0xffffffffu, acc, 2);
            if (qd == 0) sh_sc[s] = acc + ba0;
        }
        __syncthreads();

        // ---- softmax: entirely in warp 0 (no extra barriers) ----
        if (t < 32) {
            float4 v = ((const float4*)sh_sc)[t];
            float m = fmaxf(fmaxf(v.x, v.y), fmaxf(v.z, v.w));
#pragma unroll
            for (int o = 16; o; o >>= 1) m = fmaxf(m, __shfl_xor_sync(0xffffffffu, m, o));
            float4 e;
            e.x = __expf(v.x - m); e.y = __expf(v.y - m);
            e.z = __expf(v.z - m); e.w = __expf(v.w - m);
            float ssum = e.x + e.y + e.z + e.w;
#pragma unroll
            for (int o = 16; o; o >>= 1) ssum += __shfl_xor_sync(0xffffffffu, ssum, o);
            float inv = 1.f / ssum;
            e.x *= inv; e.y *= inv; e.z *= inv; e.w *= inv;
            ((float4*)sh_w)[t] = e;
        }
        __syncthreads();

        // ---- gxP = sum_s w[s]*P[b,s,:]  (768 threads, 4-way s-split, 32 iters) ----
        if (t < 768) {
            const int c = t % 192, quarter = t / 192;
            const float4* P4 = (const float4*)(P + (size_t)(b * SSQ) * 768) + c;
            float4 acc = make_float4(0.f, 0.f, 0.f, 0.f);
            const int s0 = quarter * 32;
            for (int sb = 0; sb < 32; sb += 16) {
                float4 pv[16];
#pragma unroll
                for (int i = 0; i < 16; i++) pv[i] = P4[(size_t)(s0 + sb + i) * 192];
#pragma unroll
                for (int i = 0; i < 16; i++) {
                    float ws = sh_w[s0 + sb + i];
                    acc.x = fmaf(ws, pv[i].x, acc.x); acc.y = fmaf(ws, pv[i].y, acc.y);
                    acc.z = fmaf(ws, pv[i].z, acc.z); acc.w = fmaf(ws, pv[i].w, acc.w);
                }
            }
            ((float4*)sp_gx[quarter])[c] = acc;
        }
        __syncthreads();

        // ---- gates ----
        if (t < 256) {
            const float* gxr = gx + (size_t)(ts * 32 + b) * 768;
            float ghz = sp_gh[0][t]       + sp_gh[1][t]       + sp_gh[2][t]       + sp_gh[3][t];
            float ghr = sp_gh[0][256 + t] + sp_gh[1][256 + t] + sp_gh[2][256 + t] + sp_gh[3][256 + t];
            float ghh = sp_gh[0][512 + t] + sp_gh[1][512 + t] + sp_gh[2][512 + t] + sp_gh[3][512 + t];
            float gxz = sp_gx[0][t]       + sp_gx[1][t]       + sp_gx[2][t]       + sp_gx[3][t];
            float gxrr= sp_gx[0][256 + t] + sp_gx[1][256 + t] + sp_gx[2][256 + t] + sp_gx[3][256 + t];
            float gxh = sp_gx[0][512 + t] + sp_gx[1][512 + t] + sp_gx[2][512 + t] + sp_gx[3][512 + t];
            float z  = sigmoidf_(gxr[t]       + gxz + ghz);
            float r  = sigmoidf_(gxr[256 + t] + gxrr + ghr);
            float hh = tanhf(gxr[512 + t] + gxh + r * ghh);
            float hn = z * h_old + (1.f - z) * hh;
            h_old = hn;
            Hdec[(size_t)(b * SSQ + ts) * UU + t] = hn;
            sh_h[cur ^ 1][t] = hn;
        }
        __syncthreads();
    }
}

// ---------------- launch ----------------
extern "C" void kernel_launch(void* const* d_in, const int* in_sizes, int n_in,
                              void* d_out, int out_size) {
    const int*   x         = (const int*)d_in[0];
    const int*   labels    = (const int*)d_in[1];
    const float* enc_embed = (const float*)d_in[2];
    const float* enc_Wx    = (const float*)d_in[3];
    const float* enc_Wh    = (const float*)d_in[4];
    const float* enc_b     = (const float*)d_in[5];
    const float* dec_embed = (const float*)d_in[6];
    const float* dec_Wx    = (const float*)d_in[7];
    const float* dec_Wh    = (const float*)d_in[8];
    const float* dec_b     = (const float*)d_in[9];
    const float* W1        = (const float*)d_in[10];
    const float* b1        = (const float*)d_in[11];
    const float* W2        = (const float*)d_in[12];
    const float* b2        = (const float*)d_in[13];
    const float* Va        = (const float*)d_in[14];
    const float* ba        = (const float*)d_in[15];
    const float* Wfc       = (const float*)d_in[16];
    const float* bfc       = (const float*)d_in[17];
    float* out = (float*)d_out;

    float *gxe, *gxd, *eo, *ep, *Pp, *Hd, *zb;
    __nv_bfloat16 *a2, *b2buf;
    cudaGetSymbolAddress((void**)&gxe, g_gx_enc);
    cudaGetSymbolAddress((void**)&gxd, g_gx_dec);
    cudaGetSymbolAddress((void**)&eo,  g_enc_out);
    cudaGetSymbolAddress((void**)&ep,  g_enc_proj);
    cudaGetSymbolAddress((void**)&Pp,  g_P);
    cudaGetSymbolAddress((void**)&Hd,  g_Hdec);
    cudaGetSymbolAddress((void**)&zb,  g_zb);
    cudaGetSymbolAddress((void**)&a2,  g_A2);
    cudaGetSymbolAddress((void**)&b2buf, g_B2);

    cudaFuncSetAttribute(k_fc_mma, cudaFuncAttributeMaxDynamicSharedMemorySize, 2 * FC_STAGE);

    // 1: both gx GEMMs in one launch
    k_gx_dual<<<dim3(12, 32), 256>>>(enc_embed, enc_Wx, enc_b, gxe,
                                     dec_embed, dec_Wx + 256 * 768, dec_b, gxd, x, labels);
    // 2: encoder recurrence (1024 threads)
    k_encoder<<<BB, 1024>>>(gxe, enc_Wh, eo);
    // 3: enc_proj + P in one launch
    k_proj_dual<<<dim3(8, 32), 256>>>(eo, W1, b1, ep, dec_Wx, zb, Pp);
    // 4: decoder (1024 threads)  <-- profiled launch
    k_decoder<<<BB, 1024>>>(ep, Pp, gxd, dec_Wh, W2, b2, Va, ba, eo, Hd);
    // 5: Wfc transpose + split
    k_wconv<<<dim3(VV / 64, 4), 256>>>(Wfc, b2buf);
    // 6: Hdec split
    k_hconv<<<512, 512>>>(Hd, a2);
    // 7: FC via HMMA 3-term split
    k_fc_mma<<<dim3(VV / 128, RR / 128), 256, 2 * FC_STAGE>>>(a2, b2buf, bfc, out);
}

// round 14
// speedup vs baseline: 1.3833x; 1.0101x over previous
#include <cuda_runtime.h>
#include <cuda_bf16.h>
#include <math.h>
#include <stdint.h>

#define BB 32
#define SSQ 128
#define EE 256
#define UU 256
#define VV 32000
#define RR (BB*SSQ)   // 4096

// ---------------- device scratch ----------------
__device__ float g_gx_enc[RR * 768];
__device__ float g_gx_dec[RR * 768];
__device__ float g_enc_out[RR * UU];
__device__ float g_enc_proj[RR * UU];
__device__ float g_P[RR * 768];
__device__ float g_Hdec[RR * UU];
__device__ float g_zb[768];                  // zero bias
__device__ __nv_bfloat16 g_A2[(size_t)RR * 512];
__device__ __nv_bfloat16 g_B2[(size_t)VV * 512];

__device__ __forceinline__ float sigmoidf_(float x) { return 1.0f / (1.0f + __expf(-x)); }
__device__ __forceinline__ float tanhapx(float x) {
    float y; asm("tanh.approx.f32 %0, %1;" : "=f"(y) : "f"(x)); return y;
}
__device__ __forceinline__ unsigned smem_u32(const void* p) {
    return (unsigned)__cvta_generic_to_shared(p);
}
#define CP_ASYNC16(saddr, gptr) \
    asm volatile("cp.async.ca.shared.global [%0], [%1], 16;" :: "r"(saddr), "l"(gptr))
#define CP_COMMIT()  asm volatile("cp.async.commit_group;")
#define CP_WAIT0()   asm volatile("cp.async.wait_group 0;")

#define MMA_BF16(c0, c1, c2, c3, a0, a1, a2, a3, b0, b1) \
    asm volatile("mma.sync.aligned.m16n8k16.row.col.f32.bf16.bf16.f32 " \
                 "{%0,%1,%2,%3}, {%4,%5,%6,%7}, {%8,%9}, {%0,%1,%2,%3};" \
                 : "+f"(c0), "+f"(c1), "+f"(c2), "+f"(c3) \
                 : "r"(a0), "r"(a1), "r"(a2), "r"(a3), "r"(b0), "r"(b1))

// ---------------- Wfc transpose + bf16 hi/lo split ----------------
__global__ __launch_bounds__(256)
void k_wconv(const float* __restrict__ W, __nv_bfloat16* __restrict__ B2) {
    __shared__ float tile[64][65];
    const int n0 = blockIdx.x * 64, k0 = blockIdx.y * 64;
    for (int i = threadIdx.x; i < 4096; i += 256) {
        int r = i >> 6, c = i & 63;
        tile[r][c] = W[(size_t)(k0 + r) * VV + n0 + c];
    }
    __syncthreads();
    for (int i = threadIdx.x; i < 4096; i += 256) {
        int r = i >> 6, c = i & 63;
        float v = tile[c][r];
        __nv_bfloat16 h = __float2bfloat16(v);
        __nv_bfloat16 l = __float2bfloat16(v - __bfloat162float(h));
        size_t base = (size_t)(n0 + r) * 512 + k0 + c;
        B2[base] = h;
        B2[base + 256] = l;
    }
}

// ---------------- Hdec -> A2 hi|lo ----------------
__global__ __launch_bounds__(512)
void k_hconv(const float* __restrict__ H, __nv_bfloat16* __restrict__ A2) {
    int i = (blockIdx.x * 512 + threadIdx.x) * 4;
    int row = i >> 8, k = i & 255;
    float4 v = *(const float4*)(H + i);
    __nv_bfloat16 h0 = __float2bfloat16(v.x), h1 = __float2bfloat16(v.y);
    __nv_bfloat16 h2 = __float2bfloat16(v.z), h3 = __float2bfloat16(v.w);
    __nv_bfloat16 l0 = __float2bfloat16(v.x - __bfloat162float(h0));
    __nv_bfloat16 l1 = __float2bfloat16(v.y - __bfloat162float(h1));
    __nv_bfloat16 l2 = __float2bfloat16(v.z - __bfloat162float(h2));
    __nv_bfloat16 l3 = __float2bfloat16(v.w - __bfloat162float(h3));
    __nv_bfloat162 ph0 = __halves2bfloat162(h0, h1), ph1 = __halves2bfloat162(h2, h3);
    __nv_bfloat162 pl0 = __halves2bfloat162(l0, l1), pl1 = __halves2bfloat162(l2, l3);
    size_t base = (size_t)row * 512 + k;
    *(uint2*)(A2 + base)       = make_uint2(*(uint32_t*)&ph0, *(uint32_t*)&ph1);
    *(uint2*)(A2 + base + 256) = make_uint2(*(uint32_t*)&pl0, *(uint32_t*)&pl1);
}

// ---------------- FC via HMMA 3-term split ----------------
#define FCP 144
#define FC_A_BYTES (128 * FCP)
#define FC_STAGE   (2 * FC_A_BYTES)

__device__ __forceinline__ void fc_load(char* sbase, const char* Ag, const char* Bg,
                                        int ca, int cb, int t) {
    const int ar = t >> 1, ac0 = (t & 1) * 4;
#pragma unroll
    for (int i = 0; i < 4; i++) {
        const int col16 = ac0 + i;
        const uint32_t off = (uint32_t)(ar * FCP + col16 * 16);
        CP_ASYNC16(smem_u32(sbase + off),              Ag + (size_t)ar * 1024 + ca * 128 + col16 * 16);
        CP_ASYNC16(smem_u32(sbase + FC_A_BYTES + off), Bg + (size_t)ar * 1024 + cb * 128 + col16 * 16);
    }
}

__global__ __launch_bounds__(256, 2)
void k_fc_mma(const __nv_bfloat16* __restrict__ A2, const __nv_bfloat16* __restrict__ B2,
              const float* __restrict__ bias, float* __restrict__ out) {
    extern __shared__ char smem[];
    const int t = threadIdx.x, lane = t & 31, wid = t >> 5;
    const int bm = blockIdx.y * 128, bn = blockIdx.x * 128;
    const int wm = wid & 3, wn = wid >> 2;
    const int qr = lane >> 2;
    const int qc = (lane & 3) * 2;

    const char* Ag = (const char*)(A2 + (size_t)bm * 512);
    const char* Bg = (const char*)(B2 + (size_t)bn * 512);

    float acc[2][8][4];
#pragma unroll
    for (int mf = 0; mf < 2; mf++)
#pragma unroll
        for (int nf = 0; nf < 8; nf++)
#pragma unroll
            for (int j = 0; j < 4; j++) acc[mf][nf][j] = 0.f;

    fc_load(smem, Ag, Bg, 0, 0, t);
    CP_COMMIT(); CP_WAIT0();
    __syncthreads();

    for (int c = 0; c < 12; c++) {
        const int buf = c & 1;
        if (c < 11) {
            const int p = c + 1, g = p >> 2, j = p & 3;
            fc_load(smem + (buf ^ 1) * FC_STAGE, Ag, Bg,
                    j + ((g == 2) ? 4 : 0), j + ((g == 1) ? 4 : 0), t);
            CP_COMMIT();
        }
        const char* Ab = smem + buf * FC_STAGE;
        const char* Bb = Ab + FC_A_BYTES;

#pragma unroll
        for (int ks = 0; ks < 4; ks++) {
            const int kb = (ks * 16 + qc) * 2;
            uint32_t a[2][4];
#pragma unroll
            for (int mf = 0; mf < 2; mf++) {
                const char* ap = Ab + (wm * 32 + mf * 16 + qr) * FCP + kb;
                a[mf][0] = *(const uint32_t*)(ap);
                a[mf][1] = *(const uint32_t*)(ap + 8 * FCP);
                a[mf][2] = *(const uint32_t*)(ap + 16);
                a[mf][3] = *(const uint32_t*)(ap + 8 * FCP + 16);
            }
            uint32_t bfr[8][2];
#pragma unroll
            for (int nf = 0; nf < 8; nf++) {
                const char* bp = Bb + (wn * 64 + nf * 8 + qr) * FCP + kb;
                bfr[nf][0] = *(const uint32_t*)(bp);
                bfr[nf][1] = *(const uint32_t*)(bp + 16);
            }
#pragma unroll
            for (int mf = 0; mf < 2; mf++)
#pragma unroll
                for (int nf = 0; nf < 8; nf++)
                    MMA_BF16(acc[mf][nf][0], acc[mf][nf][1], acc[mf][nf][2], acc[mf][nf][3],
                             a[mf][0], a[mf][1], a[mf][2], a[mf][3],
                             bfr[nf][0], bfr[nf][1]);
        }
        if (c < 11) CP_WAIT0();
        __syncthreads();
    }

#pragma unroll
    for (int mf = 0; mf < 2; mf++) {
        const int m0 = bm + wm * 32 + mf * 16 + qr;
#pragma unroll
        for (int nf = 0; nf < 8; nf++) {
            const int n = bn + wn * 64 + nf * 8 + qc;
            const float2 bv = *(const float2*)(bias + n);
            float2 o0, o1;
            o0.x = acc[mf][nf][0] + bv.x; o0.y = acc[mf][nf][1] + bv.y;
            o1.x = acc[mf][nf][2] + bv.x; o1.y = acc[mf][nf][3] + bv.y;
            *(float2*)(out + (size_t)m0 * VV + n) = o0;
            *(float2*)(out + (size_t)(m0 + 8) * VV + n) = o1;
        }
    }
}

// ---------------- fp32 GEMM body (device) ----------------
struct SmemGemm { float As[2][16][128]; float Bs[2][16][128]; };

template<int GATHER>
__device__ __forceinline__
void gemm_body(SmemGemm& sm, const float* __restrict__ A, const float* __restrict__ B,
               const float* __restrict__ bias, float* __restrict__ C,
               int N, int K, const int* __restrict__ toks, int bm, int bn) {
    const int t = threadIdx.x;
    const int arow = t >> 1, ak = (t & 1) * 8;
    const int brow = t >> 5, bcol = (t & 31) * 4;
    const int tm0 = (t >> 4) * 8, tn0 = (t & 15) * 8;

    const float* Abase;
    if (GATHER == 0) {
        Abase = A + (size_t)(bm + arow) * K;
    } else {
        int r = bm + arow, s = r >> 5, b = r & 31;
        int tok;
        if (GATHER == 1) tok = toks[b * SSQ + s];
        else             tok = (s == 0) ? 0 : toks[b * SSQ + s - 1];
        Abase = A + (size_t)tok * K;
    }
    const float* Bbase = B + (size_t)brow * N + bn + bcol;

    float acc[8][8];
#pragma unroll
    for (int i = 0; i < 8; i++)
#pragma unroll
        for (int j = 0; j < 8; j++) acc[i][j] = 0.f;

    float4 av0 = *(const float4*)(Abase + ak);
    float4 av1 = *(const float4*)(Abase + ak + 4);
    CP_ASYNC16(smem_u32(&sm.Bs[0][brow][bcol]), Bbase);
    CP_ASYNC16(smem_u32(&sm.Bs[0][brow + 8][bcol]), Bbase + (size_t)8 * N);
    CP_COMMIT();
    sm.As[0][ak + 0][arow] = av0.x; sm.As[0][ak + 1][arow] = av0.y;
    sm.As[0][ak + 2][arow] = av0.z; sm.As[0][ak + 3][arow] = av0.w;
    sm.As[0][ak + 4][arow] = av1.x; sm.As[0][ak + 5][arow] = av1.y;
    sm.As[0][ak + 6][arow] = av1.z; sm.As[0][ak + 7][arow] = av1.w;
    CP_WAIT0();
    __syncthreads();

    const int NT = K >> 4;
    for (int kt = 0; kt < NT; kt++) {
        const int buf = kt & 1, nxt = buf ^ 1;
        const bool more = (kt + 1 < NT);
        if (more) {
            const float* Ap = Abase + (kt + 1) * 16;
            av0 = *(const float4*)(Ap + ak);
            av1 = *(const float4*)(Ap + ak + 4);
            const float* Bp = Bbase + (size_t)(kt + 1) * 16 * N;
            CP_ASYNC16(smem_u32(&sm.Bs[nxt][brow][bcol]), Bp);
            CP_ASYNC16(smem_u32(&sm.Bs[nxt][brow + 8][bcol]), Bp + (size_t)8 * N);
            CP_COMMIT();
        }
#pragma unroll
        for (int kk = 0; kk < 16; kk++) {
            float a[8], bf[8];
            *(float4*)&a[0]  = *(const float4*)&sm.As[buf][kk][tm0];
            *(float4*)&a[4]  = *(const float4*)&sm.As[buf][kk][tm0 + 4];
            *(float4*)&bf[0] = *(const float4*)&sm.Bs[buf][kk][tn0];
            *(float4*)&bf[4] = *(const float4*)&sm.Bs[buf][kk][tn0 + 4];
#pragma unroll
            for (int i = 0; i < 8; i++)
#pragma unroll
                for (int j = 0; j < 8; j++)
                    acc[i][j] = fmaf(a[i], bf[j], acc[i][j]);
        }
        if (more) {
            sm.As[nxt][ak + 0][arow] = av0.x; sm.As[nxt][ak + 1][arow] = av0.y;
            sm.As[nxt][ak + 2][arow] = av0.z; sm.As[nxt][ak + 3][arow] = av0.w;
            sm.As[nxt][ak + 4][arow] = av1.x; sm.As[nxt][ak + 5][arow] = av1.y;
            sm.As[nxt][ak + 6][arow] = av1.z; sm.As[nxt][ak + 7][arow] = av1.w;
            CP_WAIT0();
        }
        __syncthreads();
    }

#pragma unroll
    for (int i = 0; i < 8; i++) {
        float* Crow = C + (size_t)(bm + tm0 + i) * N + bn + tn0;
#pragma unroll
        for (int j = 0; j < 8; j += 4) {
            float4 o;
            o.x = acc[i][j + 0] + bias[bn + tn0 + j + 0];
            o.y = acc[i][j + 1] + bias[bn + tn0 + j + 1];
            o.z = acc[i][j + 2] + bias[bn + tn0 + j + 2];
            o.w = acc[i][j + 3] + bias[bn + tn0 + j + 3];
            *(float4*)(Crow + j) = o;
        }
    }
}

// dual-GEMM 1: gx_enc (blocks x<6) + gx_dec (blocks x>=6)
__global__ __launch_bounds__(256, 2)
void k_gx_dual(const float* __restrict__ enc_embed, const float* __restrict__ enc_Wx,
               const float* __restrict__ enc_b, float* __restrict__ gxe,
               const float* __restrict__ dec_embed, const float* __restrict__ dec_WxE,
               const float* __restrict__ dec_b, float* __restrict__ gxd,
               const int* __restrict__ x, const int* __restrict__ labels) {
    __shared__ SmemGemm sm;
    const int bm = blockIdx.y * 128;
    if (blockIdx.x < 6)
        gemm_body<1>(sm, enc_embed, enc_Wx, enc_b, gxe, 768, 256, x, bm, blockIdx.x * 128);
    else
        gemm_body<2>(sm, dec_embed, dec_WxE, dec_b, gxd, 768, 256, labels, bm, (blockIdx.x - 6) * 128);
}

// dual-GEMM 2: enc_proj (blocks x<2) + P (blocks x>=2)
__global__ __launch_bounds__(256, 2)
void k_proj_dual(const float* __restrict__ eo,
                 const float* __restrict__ W1, const float* __restrict__ b1, float* __restrict__ ep,
                 const float* __restrict__ dec_Wx, const float* __restrict__ zb, float* __restrict__ P) {
    __shared__ SmemGemm sm;
    const int bm = blockIdx.y * 128;
    if (blockIdx.x < 2)
        gemm_body<0>(sm, eo, W1, b1, ep, 256, 256, nullptr, bm, blockIdx.x * 128);
    else
        gemm_body<0>(sm, eo, dec_Wx, zb, P, 768, 256, nullptr, bm, (blockIdx.x - 2) * 128);
}

// ---------------- encoder GRU: 1024 threads, 4-way k-split (64 iters) ----------------
__global__ __launch_bounds__(1024)
void k_encoder(const float* __restrict__ gx, const float* __restrict__ Wh,
               float* __restrict__ enc_out) {
    __shared__ float sh_h[2][UU];
    __shared__ float sp[4][768];
    const int b = blockIdx.x, t = threadIdx.x;
    float h_old = 0.f;
    if (t < 256) sh_h[0][t] = 0.f;
    __syncthreads();
    for (int s = 0; s < SSQ; s++) {
        const int cur = s & 1;
        if (t < 768) {
            const int c = t % 192, quarter = t / 192;
            const float4* W4 = (const float4*)Wh + c;
            float4 acc = make_float4(0.f, 0.f, 0.f, 0.f);
            const int k0 = quarter * 64;
            for (int kb = 0; kb < 64; kb += 16) {
                float4 wv[16];
#pragma unroll
                for (int i = 0; i < 16; i++) wv[i] = W4[(size_t)(k0 + kb + i) * 192];
#pragma unroll
                for (int i = 0; i < 16; i++) {
                    float hk = sh_h[cur][k0 + kb + i];
                    acc.x = fmaf(hk, wv[i].x, acc.x); acc.y = fmaf(hk, wv[i].y, acc.y);
                    acc.z = fmaf(hk, wv[i].z, acc.z); acc.w = fmaf(hk, wv[i].w, acc.w);
                }
            }
            ((float4*)sp[quarter])[c] = acc;
        }
        __syncthreads();
        if (t < 256) {
            const float* gxr = gx + (size_t)(s * 32 + b) * 768;
            float ghz = sp[0][t]       + sp[1][t]       + sp[2][t]       + sp[3][t];
            float ghr = sp[0][256 + t] + sp[1][256 + t] + sp[2][256 + t] + sp[3][256 + t];
            float ghh = sp[0][512 + t] + sp[1][512 + t] + sp[2][512 + t] + sp[3][512 + t];
            float z  = sigmoidf_(gxr[t]       + ghz);
            float r  = sigmoidf_(gxr[256 + t] + ghr);
            float hh = tanhf(gxr[512 + t] + r * ghh);
            float hn = z * h_old + (1.f - z) * hh;
            h_old = hn;
            enc_out[(size_t)(b * SSQ + s) * UU + t] = hn;
            sh_h[cur ^ 1][t] = hn;
        }
        __syncthreads();
    }
}

// ---------------- decoder: 1024 threads, 4-way splits, warp0 softmax ----------------
__global__ __launch_bounds__(1024)
void k_decoder(const float* __restrict__ enc_proj, const float* __restrict__ P,
               const float* __restrict__ gx, const float* __restrict__ dec_Wh,
               const float* __restrict__ W2, const float* __restrict__ b2,
               const float* __restrict__ Va, const float* __restrict__ ba,
               const float* __restrict__ enc_out, float* __restrict__ Hdec) {
    __shared__ float sh_h[2][UU];
    __shared__ float sh_q[UU];
    __shared__ float sh_Va[UU];
    __shared__ float sh_sc[SSQ];
    __shared__ float sh_w[SSQ];
    __shared__ float sp_q[4][UU];
    __shared__ float sp_gh[4][768];
    __shared__ float sp_gx[4][768];

    const int b = blockIdx.x, t = threadIdx.x;
    float h_old = 0.f;
    if (t < 256) {
        sh_Va[t] = Va[t];
        h_old = enc_out[(size_t)(b * SSQ + 127) * UU + t];
        sh_h[0][t] = h_old;
    }
    const float ba0 = ba[0];
    __syncthreads();

    for (int ts = 0; ts < SSQ; ts++) {
        const int cur = ts & 1;
        // ---- Phase A: q (t<256, 4-way k) || gh (t in [256,1024), 4-way k) ----
        if (t < 256) {
            const int c = t & 63, quarter = t >> 6;
            const float4* W4 = (const float4*)W2 + c;
            float4 acc = make_float4(0.f, 0.f, 0.f, 0.f);
            const int k0 = quarter * 64;
            for (int kb = 0; kb < 64; kb += 16) {
                float4 wv[16];
#pragma unroll
                for (int i = 0; i < 16; i++) wv[i] = W4[(size_t)(k0 + kb + i) * 64];
#pragma unroll
                for (int i = 0; i < 16; i++) {
                    float hk = sh_h[cur][k0 + kb + i];
                    acc.x = fmaf(hk, wv[i].x, acc.x); acc.y = fmaf(hk, wv[i].y, acc.y);
                    acc.z = fmaf(hk, wv[i].z, acc.z); acc.w = fmaf(hk, wv[i].w, acc.w);
                }
            }
            if (quarter == 0) {
                float4 bb = ((const float4*)b2)[c];
                acc.x += bb.x; acc.y += bb.y; acc.z += bb.z; acc.w += bb.w;
            }
            ((float4*)sp_q[quarter])[c] = acc;
        } else {
            const int u = t - 256;
            const int c = u % 192, quarter = u / 192;
            const float4* Wh4 = (const float4*)dec_Wh + c;
            float4 acc = make_float4(0.f, 0.f, 0.f, 0.f);
            const int k0 = quarter * 64;
            for (int kb = 0; kb < 64; kb += 16) {
                float4 wv[16];
#pragma unroll
                for (int i = 0; i < 16; i++) wv[i] = Wh4[(size_t)(k0 + kb + i) * 192];
#pragma unroll
                for (int i = 0; i < 16; i++) {
                    float hk = sh_h[cur][k0 + kb + i];
                    acc.x = fmaf(hk, wv[i].x, acc.x); acc.y = fmaf(hk, wv[i].y, acc.y);
                    acc.z = fmaf(hk, wv[i].z, acc.z); acc.w = fmaf(hk, wv[i].w, acc.w);
                }
            }
            ((float4*)sp_gh[quarter])[c] = acc;
        }
        __syncthreads();

        // ---- q-sum (64 threads) ----
        if (t < 64) {
            float4 a0 = ((const float4*)sp_q[0])[t];
            float4 a1 = ((const float4*)sp_q[1])[t];
            float4 a2 = ((const float4*)sp_q[2])[t];
            float4 a3 = ((const float4*)sp_q[3])[t];
            float4 o;
            o.x = a0.x + a1.x + a2.x + a3.x;
            o.y = a0.y + a1.y + a2.y + a3.y;
            o.z = a0.z + a1.z + a2.z + a3.z;
            o.w = a0.w + a1.w + a2.w + a3.w;
            ((float4*)sh_q)[t] = o;
        }
        __syncthreads();

        // ---- attention scores (512 threads: 4/s, MUFU floor anyway) ----
        if (t < 512) {
            const int s = t >> 2, qd = t & 3;
            const float4* ep = (const float4*)(enc_proj + (size_t)(b * SSQ + s) * UU) + qd * 16;
            const float4* q4 = (const float4*)sh_q + qd * 16;
            const float4* v4 = (const float4*)sh_Va + qd * 16;
            float acc = 0.f;
#pragma unroll 16
            for (int i = 0; i < 16; i++) {
                float4 p = ep[i], qa = q4[i], vv = v4[i];
                acc += tanhapx(p.x + qa.x) * vv.x;
                acc += tanhapx(p.y + qa.y) * vv.y;
                acc += tanhapx(p.z + qa.z) * vv.z;
                acc += tanhapx(p.w + qa.w) * vv.w;
            }
            acc += __shfl_xor_sync(0xffffffffu, acc, 1);
            acc += __shfl_xor_sync(0xffffffffu, acc, 2);
            if (qd == 0) sh_sc[s] = acc + ba0;
        }
        __syncthreads();

        // ---- softmax: entirely in warp 0 (no extra barriers) ----
        if (t < 32) {
            float4 v = ((const float4*)sh_sc)[t];
            float m = fmaxf(fmaxf(v.x, v.y), fmaxf(v.z, v.w));
#pragma unroll
            for (int o = 16; o; o >>= 1) m = fmaxf(m, __shfl_xor_sync(0xffffffffu, m, o));
            float4 e;
            e.x = __expf(v.x - m); e.y = __expf(v.y - m);
            e.z = __expf(v.z - m); e.w = __expf(v.w - m);
            float ssum = e.x + e.y + e.z + e.w;
#pragma unroll
            for (int o = 16; o; o >>= 1) ssum += __shfl_xor_sync(0xffffffffu, ssum, o);
            float inv = 1.f / ssum;
            e.x *= inv; e.y *= inv; e.z *= inv; e.w *= inv;
            ((float4*)sh_w)[t] = e;
        }
        __syncthreads();

        // ---- gxP = sum_s w[s]*P[b,s,:]  (768 threads, 4-way s-split, 32 iters) ----
        if (t < 768) {
            const int c = t % 192, quarter = t / 192;
            const float4* P4 = (const float4*)(P + (size_t)(b * SSQ) * 768) + c;
            float4 acc = make_float4(0.f, 0.f, 0.f, 0.f);
            const int s0 = quarter * 32;
            for (int sb = 0; sb < 32; sb += 16) {
                float4 pv[16];
#pragma unroll
                for (int i = 0; i < 16; i++) pv[i] = P4[(size_t)(s0 + sb + i) * 192];
#pragma unroll
                for (int i = 0; i < 16; i++) {
                    float ws = sh_w[s0 + sb + i];
                    acc.x = fmaf(ws, pv[i].x, acc.x); acc.y = fmaf(ws, pv[i].y, acc.y);
                    acc.z = fmaf(ws, pv[i].z, acc.z); acc.w = fmaf(ws, pv[i].w, acc.w);
                }
            }
            ((float4*)sp_gx[quarter])[c] = acc;
        }
        __syncthreads();

        // ---- gates ----
        if (t < 256) {
            const float* gxr = gx + (size_t)(ts * 32 + b) * 768;
            float ghz = sp_gh[0][t]       + sp_gh[1][t]       + sp_gh[2][t]       + sp_gh[3][t];
            float ghr = sp_gh[0][256 + t] + sp_gh[1][256 + t] + sp_gh[2][256 + t] + sp_gh[3][256 + t];
            float ghh = sp_gh[0][512 + t] + sp_gh[1][512 + t] + sp_gh[2][512 + t] + sp_gh[3][512 + t];
            float gxz = sp_gx[0][t]       + sp_gx[1][t]       + sp_gx[2][t]       + sp_gx[3][t];
            float gxrr= sp_gx[0][256 + t] + sp_gx[1][256 + t] + sp_gx[2][256 + t] + sp_gx[3][256 + t];
            float gxh = sp_gx[0][512 + t] + sp_gx[1][512 + t] + sp_gx[2][512 + t] + sp_gx[3][512 + t];
            float z  = sigmoidf_(gxr[t]       + gxz + ghz);
            float r  = sigmoidf_(gxr[256 + t] + gxrr + ghr);
            float hh = tanhf(gxr[512 + t] + gxh + r * ghh);
            float hn = z * h_old + (1.f - z) * hh;
            h_old = hn;
            Hdec[(size_t)(b * SSQ + ts) * UU + t] = hn;
            sh_h[cur ^ 1][t] = hn;
        }
        __syncthreads();
    }
}

// ---------------- launch ----------------
extern "C" void kernel_launch(void* const* d_in, const int* in_sizes, int n_in,
                              void* d_out, int out_size) {
    const int*   x         = (const int*)d_in[0];
    const int*   labels    = (const int*)d_in[1];
    const float* enc_embed = (const float*)d_in[2];
    const float* enc_Wx    = (const float*)d_in[3];
    const float* enc_Wh    = (const float*)d_in[4];
    const float* enc_b     = (const float*)d_in[5];
    const float* dec_embed = (const float*)d_in[6];
    const float* dec_Wx    = (const float*)d_in[7];
    const float* dec_Wh    = (const float*)d_in[8];
    const float* dec_b     = (const float*)d_in[9];
    const float* W1        = (const float*)d_in[10];
    const float* b1        = (const float*)d_in[11];
    const float* W2        = (const float*)d_in[12];
    const float* b2        = (const float*)d_in[13];
    const float* Va        = (const float*)d_in[14];
    const float* ba        = (const float*)d_in[15];
    const float* Wfc       = (const float*)d_in[16];
    const float* bfc       = (const float*)d_in[17];
    float* out = (float*)d_out;

    float *gxe, *gxd, *eo, *ep, *Pp, *Hd, *zb;
    __nv_bfloat16 *a2, *b2buf;
    cudaGetSymbolAddress((void**)&gxe, g_gx_enc);
    cudaGetSymbolAddress((void**)&gxd, g_gx_dec);
    cudaGetSymbolAddress((void**)&eo,  g_enc_out);
    cudaGetSymbolAddress((void**)&ep,  g_enc_proj);
    cudaGetSymbolAddress((void**)&Pp,  g_P);
    cudaGetSymbolAddress((void**)&Hd,  g_Hdec);
    cudaGetSymbolAddress((void**)&zb,  g_zb);
    cudaGetSymbolAddress((void**)&a2,  g_A2);
    cudaGetSymbolAddress((void**)&b2buf, g_B2);

    cudaFuncSetAttribute(k_fc_mma, cudaFuncAttributeMaxDynamicSharedMemorySize, 2 * FC_STAGE);

    // 1: both gx GEMMs in one launch
    k_gx_dual<<<dim3(12, 32), 256>>>(enc_embed, enc_Wx, enc_b, gxe,
                                     dec_embed, dec_Wx + 256 * 768, dec_b, gxd, x, labels);
    // 2: encoder recurrence (1024 threads)
    k_encoder<<<BB, 1024>>>(gxe, enc_Wh, eo);
    // 3: enc_proj + P in one launch
    k_proj_dual<<<dim3(8, 32), 256>>>(eo, W1, b1, ep, dec_Wx, zb, Pp);
    // 4: decoder (1024 threads)  <-- profiled launch
    k_decoder<<<BB, 1024>>>(ep, Pp, gxd, dec_Wh, W2, b2, Va, ba, eo, Hd);
    // 5: Wfc transpose + split
    k_wconv<<<dim3(VV / 64, 4), 256>>>(Wfc, b2buf);
    // 6: Hdec split
    k_hconv<<<512, 512>>>(Hd, a2);
    // 7: FC via HMMA 3-term split
    k_fc_mma<<<dim3(VV / 128, RR / 128), 256, 2 * FC_STAGE>>>(a2, b2buf, bfc, out);
}